// round 5
// baseline (speedup 1.0000x reference)
#include <cuda_runtime.h>
#include <cstdint>
#include <cstddef>

#define BB 2
#define NTOK 1569
#define CC 768
#define HH 12
#define PP 196
#define FF 8
#define SS 1568
#define SCALE 0.125f

// ---------------- scratch (static device globals: no allocation) ----------------
__device__ float g_qkv[(size_t)BB * NTOK * 3 * CC];   // (B*N, 2304)
__device__ float g_traj[(size_t)BB * SS * FF * CC];   // (B,S,F,C)
__device__ float g_xd[(size_t)BB * SS * CC];          // x_diag (B,S,C)
__device__ float g_q2v[(size_t)BB * SS * CC];         // q2 (B,S,C) head-major, pre-scaled
__device__ float g_gb[(size_t)BB * SS * HH * CC];     // g (B,S,H,C)
__device__ float g_pre[(size_t)BB * NTOK * CC];       // concat(cls_out, out)

// ---------------- generic SGEMM: C = alpha * A(MxK)@B(KxN) (+bias) ----------------
// Requirements: N % 128 == 0, K % 8 == 0. M edge guarded.
__global__ void __launch_bounds__(256) sgemm_kernel(
    const float* __restrict__ A, const float* __restrict__ B, float* __restrict__ C,
    int M, int N, int K, float alpha, const float* __restrict__ bias)
{
    __shared__ float As[8][132];
    __shared__ float Bs[8][128];
    const int tid = threadIdx.x;
    const int tx = tid & 15;
    const int ty = tid >> 4;
    const int row0 = blockIdx.y * 128;
    const int col0 = blockIdx.x * 128;

    float acc[8][8];
#pragma unroll
    for (int i = 0; i < 8; i++)
#pragma unroll
        for (int j = 0; j < 8; j++) acc[i][j] = 0.f;

    const int a_row = tid >> 1;           // 0..127
    const int a_col = (tid & 1) * 4;      // 0 or 4
    const int b_row = tid >> 5;           // 0..7
    const int b_col = (tid & 31) * 4;     // 0..124
    const int m_glob = row0 + a_row;

    for (int k0 = 0; k0 < K; k0 += 8) {
        float4 av = make_float4(0.f, 0.f, 0.f, 0.f);
        if (m_glob < M)
            av = *(const float4*)(A + (size_t)m_glob * K + k0 + a_col);
        As[a_col + 0][a_row] = av.x;
        As[a_col + 1][a_row] = av.y;
        As[a_col + 2][a_row] = av.z;
        As[a_col + 3][a_row] = av.w;
        *(float4*)&Bs[b_row][b_col] =
            *(const float4*)(B + (size_t)(k0 + b_row) * N + col0 + b_col);
        __syncthreads();
#pragma unroll
        for (int kk = 0; kk < 8; kk++) {
            float a[8], b[8];
            *(float4*)&a[0] = *(float4*)&As[kk][ty * 4];
            *(float4*)&a[4] = *(float4*)&As[kk][64 + ty * 4];
            *(float4*)&b[0] = *(float4*)&Bs[kk][tx * 4];
            *(float4*)&b[4] = *(float4*)&Bs[kk][64 + tx * 4];
#pragma unroll
            for (int i = 0; i < 8; i++)
#pragma unroll
                for (int j = 0; j < 8; j++)
                    acc[i][j] += a[i] * b[j];
        }
        __syncthreads();
    }

#pragma unroll
    for (int i = 0; i < 8; i++) {
        int r = row0 + ((i < 4) ? (ty * 4 + i) : (64 + ty * 4 + (i - 4)));
        if (r >= M) continue;
#pragma unroll
        for (int jb = 0; jb < 2; jb++) {
            int cb = col0 + jb * 64 + tx * 4;
            float4 v;
            v.x = acc[i][jb * 4 + 0] * alpha;
            v.y = acc[i][jb * 4 + 1] * alpha;
            v.z = acc[i][jb * 4 + 2] * alpha;
            v.w = acc[i][jb * 4 + 3] * alpha;
            if (bias) {
                v.x += bias[cb + 0]; v.y += bias[cb + 1];
                v.z += bias[cb + 2]; v.w += bias[cb + 3];
            }
            *(float4*)(C + (size_t)r * N + cb) = v;
        }
    }
}

// ---------------- CLS attention: one block per (b,h) ----------------
__global__ void __launch_bounds__(256) cls_kernel(const float* __restrict__ qkv,
                                                  float* __restrict__ pre)
{
    __shared__ float qv[64];
    __shared__ float logit[NTOK];
    __shared__ float red[256];
    const int bh = blockIdx.x;
    const int b = bh / HH, h = bh % HH;
    const int t = threadIdx.x;
    const float* base = qkv + (size_t)b * NTOK * (3 * CC);

    if (t < 64) qv[t] = base[h * 64 + t] * SCALE;   // q of CLS token, pre-scaled
    __syncthreads();

    for (int n = t; n < NTOK; n += 256) {
        const float* kr = base + (size_t)n * (3 * CC) + CC + h * 64;
        float s = 0.f;
#pragma unroll 16
        for (int dd = 0; dd < 64; dd++) s += qv[dd] * kr[dd];
        logit[n] = s;
    }
    __syncthreads();

    float m = -1e30f;
    for (int n = t; n < NTOK; n += 256) m = fmaxf(m, logit[n]);
    red[t] = m; __syncthreads();
    for (int s2 = 128; s2 > 0; s2 >>= 1) {
        if (t < s2) red[t] = fmaxf(red[t], red[t + s2]);
        __syncthreads();
    }
    const float mx = red[0];
    __syncthreads();

    float ssum = 0.f;
    for (int n = t; n < NTOK; n += 256) {
        float e = __expf(logit[n] - mx);
        logit[n] = e;
        ssum += e;
    }
    red[t] = ssum; __syncthreads();
    for (int s2 = 128; s2 > 0; s2 >>= 1) {
        if (t < s2) red[t] += red[t + s2];
        __syncthreads();
    }
    const float inv = 1.f / red[0];
    __syncthreads();

    // weighted sum over v
    const int dd = t & 63, grp = t >> 6;
    float acc = 0.f;
    for (int n = grp; n < NTOK; n += 4)
        acc += logit[n] * base[(size_t)n * (3 * CC) + 2 * CC + h * 64 + dd];
    red[t] = acc; __syncthreads();
    if (t < 64) {
        float v = red[t] + red[t + 64] + red[t + 128] + red[t + 192];
        pre[(size_t)b * NTOK * CC + h * 64 + t] = v * inv;
    }
}

// ---------------- fused per-frame spatial attention ----------------
// grid: (S/32, F, B*H), 128 threads.
// dyn smem: qs[64][32] | ls[32][197] | kv[64*197] (k transposed, then reused as v[n][64])
#define SPA_SMEM_FLOATS (2048 + 32 * 197 + 64 * 197)
__global__ void __launch_bounds__(128) spatial_kernel(const float* __restrict__ qkv,
                                                      float* __restrict__ traj)
{
    extern __shared__ float sm[];
    float* qs = sm;                       // 2048 : qs[dd*32 + q], pre-scaled
    float* ls = sm + 2048;                // 32*197
    float* kv = sm + 2048 + 32 * 197;     // 64*197

    const int t = threadIdx.x;
    const int bh = blockIdx.z;
    const int b = bh / HH, h = bh % HH;
    const int f = blockIdx.y;
    const int q0 = blockIdx.x * 32;
    const float* base = qkv + (size_t)b * NTOK * (3 * CC);

    // load q tile (transposed, scaled)
    for (int idx = t; idx < 512; idx += 128) {
        int q = idx >> 4;
        int dv = (idx & 15) * 4;
        float4 v = *(const float4*)(base + (size_t)(1 + q0 + q) * (3 * CC) + h * 64 + dv);
        qs[(dv + 0) * 32 + q] = v.x * SCALE;
        qs[(dv + 1) * 32 + q] = v.y * SCALE;
        qs[(dv + 2) * 32 + q] = v.z * SCALE;
        qs[(dv + 3) * 32 + q] = v.w * SCALE;
    }
    // load k frame (transposed): kv[dd*197 + n]
    for (int idx = t; idx < PP * 16; idx += 128) {
        int n = idx >> 4;
        int dv = (idx & 15) * 4;
        float4 v = *(const float4*)(base + (size_t)(1 + f * PP + n) * (3 * CC) + CC + h * 64 + dv);
        kv[(dv + 0) * 197 + n] = v.x;
        kv[(dv + 1) * 197 + n] = v.y;
        kv[(dv + 2) * 197 + n] = v.z;
        kv[(dv + 3) * 197 + n] = v.w;
    }
    __syncthreads();

    // QK: thread (ty 0..3, tx 0..31), micro 8q x 7n (n = tx + 32j)
    {
        const int tx = t & 31, ty = t >> 5;
        float acc[8][7];
#pragma unroll
        for (int i = 0; i < 8; i++)
#pragma unroll
            for (int j = 0; j < 7; j++) acc[i][j] = 0.f;
#pragma unroll 4
        for (int kk = 0; kk < 64; kk++) {
            float a[8];
#pragma unroll
            for (int i = 0; i < 8; i++) a[i] = qs[kk * 32 + ty * 8 + i];
#pragma unroll
            for (int j = 0; j < 6; j++) {
                float bv = kv[kk * 197 + tx + 32 * j];
#pragma unroll
                for (int i = 0; i < 8; i++) acc[i][j] += a[i] * bv;
            }
            if (tx < 4) {
                float bv = kv[kk * 197 + tx + 192];
#pragma unroll
                for (int i = 0; i < 8; i++) acc[i][6] += a[i] * bv;
            }
        }
#pragma unroll
        for (int i = 0; i < 8; i++) {
#pragma unroll
            for (int j = 0; j < 6; j++)
                ls[(ty * 8 + i) * 197 + tx + 32 * j] = acc[i][j];
            if (tx < 4) ls[(ty * 8 + i) * 197 + tx + 192] = acc[i][6];
        }
    }
    __syncthreads();

    // softmax over n (196) per q: warp handles 8 queries
    {
        const int lane = t & 31, w = t >> 5;
        for (int qq = w * 8; qq < w * 8 + 8; qq++) {
            float* row = ls + qq * 197;
            float m = -1e30f;
            for (int n = lane; n < PP; n += 32) m = fmaxf(m, row[n]);
#pragma unroll
            for (int o = 16; o; o >>= 1) m = fmaxf(m, __shfl_xor_sync(0xffffffffu, m, o));
            float s = 0.f;
            for (int n = lane; n < PP; n += 32) {
                float e = __expf(row[n] - m);
                row[n] = e;
                s += e;
            }
#pragma unroll
            for (int o = 16; o; o >>= 1) s += __shfl_xor_sync(0xffffffffu, s, o);
            float inv = 1.f / s;
            for (int n = lane; n < PP; n += 32) row[n] *= inv;
        }
    }
    __syncthreads();

    // load v frame into kv (reuse) as vs[n*64 + dd]
    for (int idx = t; idx < PP * 16; idx += 128) {
        int n = idx >> 4;
        int dv = (idx & 15) * 4;
        *(float4*)(kv + n * 64 + dv) =
            *(const float4*)(base + (size_t)(1 + f * PP + n) * (3 * CC) + 2 * CC + h * 64 + dv);
    }
    __syncthreads();

    // PV: thread (ty2 0..7, tx2 0..15), micro 4q x 4dd
    {
        const int tx2 = t & 15, ty2 = t >> 4;
        float acc[4][4];
#pragma unroll
        for (int i = 0; i < 4; i++)
#pragma unroll
            for (int j = 0; j < 4; j++) acc[i][j] = 0.f;
        for (int n = 0; n < PP; n++) {
            float a[4];
#pragma unroll
            for (int i = 0; i < 4; i++) a[i] = ls[(ty2 * 4 + i) * 197 + n];
            float4 bv = *(float4*)(kv + n * 64 + tx2 * 4);
#pragma unroll
            for (int i = 0; i < 4; i++) {
                acc[i][0] += a[i] * bv.x;
                acc[i][1] += a[i] * bv.y;
                acc[i][2] += a[i] * bv.z;
                acc[i][3] += a[i] * bv.w;
            }
        }
#pragma unroll
        for (int i = 0; i < 4; i++) {
            int s = q0 + ty2 * 4 + i;
            float4 o = make_float4(acc[i][0], acc[i][1], acc[i][2], acc[i][3]);
            *(float4*)(traj + (((size_t)(b * SS + s) * FF + f) * CC + h * 64 + tx2 * 4)) = o;
        }
    }
}

// ---------------- x_diag gather ----------------
__global__ void xdiag_kernel(const float* __restrict__ traj, float* __restrict__ xd)
{
    int i = blockIdx.x * blockDim.x + threadIdx.x;
    const int TOT = BB * SS * (CC / 4);
    if (i >= TOT) return;
    int bs = i / (CC / 4);
    int c4 = i - bs * (CC / 4);
    int s = bs % SS;
    int f = s / PP;
    ((float4*)xd)[(size_t)bs * (CC / 4) + c4] =
        ((const float4*)traj)[((size_t)bs * FF + f) * (CC / 4) + c4];
}

// ---------------- g[b,s,h,c] = sum_d q2[bs, h*64+d] * W_pkv[c, h*64+d] ----------------
// grid: (B*S/64, C/64, H), 256 threads, NT-GEMM with K=64
__global__ void __launch_bounds__(256) g_kernel(
    const float* __restrict__ q2, const float* __restrict__ Wpkv, float* __restrict__ g)
{
    __shared__ float As[64 * 65];
    __shared__ float Bs[64 * 65];
    const int t = threadIdx.x;
    const int m0 = blockIdx.x * 64;
    const int n0 = blockIdx.y * 64;
    const int h = blockIdx.z;

#pragma unroll
    for (int r = 0; r < 4; r++) {
        int idx = t + r * 256;
        int mm = idx >> 4;
        int dv = (idx & 15) * 4;
        float4 a = *(const float4*)(q2 + (size_t)(m0 + mm) * CC + h * 64 + dv);
        As[mm * 65 + dv + 0] = a.x;
        As[mm * 65 + dv + 1] = a.y;
        As[mm * 65 + dv + 2] = a.z;
        As[mm * 65 + dv + 3] = a.w;
        float4 bv = *(const float4*)(Wpkv + (size_t)(n0 + mm) * (2 * CC) + h * 64 + dv);
        Bs[mm * 65 + dv + 0] = bv.x;
        Bs[mm * 65 + dv + 1] = bv.y;
        Bs[mm * 65 + dv + 2] = bv.z;
        Bs[mm * 65 + dv + 3] = bv.w;
    }
    __syncthreads();

    const int tx = t & 15, ty = t >> 4;
    float acc[4][4];
#pragma unroll
    for (int i = 0; i < 4; i++)
#pragma unroll
        for (int j = 0; j < 4; j++) acc[i][j] = 0.f;
#pragma unroll 8
    for (int kk = 0; kk < 64; kk++) {
        float a[4], b[4];
#pragma unroll
        for (int i = 0; i < 4; i++) a[i] = As[(ty * 4 + i) * 65 + kk];
#pragma unroll
        for (int j = 0; j < 4; j++) b[j] = Bs[(tx * 4 + j) * 65 + kk];
#pragma unroll
        for (int i = 0; i < 4; i++)
#pragma unroll
            for (int j = 0; j < 4; j++) acc[i][j] += a[i] * b[j];
    }
#pragma unroll
    for (int i = 0; i < 4; i++) {
        float4 v = make_float4(acc[i][0], acc[i][1], acc[i][2], acc[i][3]);
        *(float4*)(g + ((size_t)(m0 + ty * 4 + i) * HH + h) * CC + n0 + tx * 4) = v;
    }
}

// ---------------- phase-2: logits + softmax + output + attn write ----------------
// grid: B*S blocks, 256 threads. dyn smem: traj 8*768 | g 12*768 | logits 96 | attn 96
#define P2_SMEM_FLOATS (FF * CC + HH * CC + 96 + 96)
__global__ void __launch_bounds__(256) phase2_kernel(
    const float* __restrict__ traj, const float* __restrict__ g,
    float* __restrict__ pre, float* __restrict__ attn_out, int write_attn)
{
    extern __shared__ float sm[];
    float* trs = sm;                  // 6144
    float* gs = sm + FF * CC;         // 9216
    float* lsm = gs + HH * CC;        // 96
    float* am = lsm + 96;             // 96

    const int bs = blockIdx.x;
    const int b = bs / SS, s = bs % SS;
    const int t = threadIdx.x;

    const float* tr = traj + (size_t)bs * FF * CC;
    for (int i = t; i < FF * CC / 4; i += 256)
        ((float4*)trs)[i] = ((const float4*)tr)[i];
    const float* gg = g + (size_t)bs * HH * CC;
    for (int i = t; i < HH * CC / 4; i += 256)
        ((float4*)gs)[i] = ((const float4*)gg)[i];
    __syncthreads();

    // logits: 96 (h,f) pairs, 12 per warp
    {
        const int lane = t & 31, w = t >> 5;
        for (int p = w * 12; p < w * 12 + 12; p++) {
            int h = p >> 3, f = p & 7;
            float ssum = 0.f;
            for (int c = lane; c < CC; c += 32)
                ssum += trs[f * CC + c] * gs[h * CC + c];
#pragma unroll
            for (int o = 16; o; o >>= 1) ssum += __shfl_xor_sync(0xffffffffu, ssum, o);
            if (lane == 0) lsm[p] = ssum;
        }
    }
    __syncthreads();

    if (t < HH) {
        int h = t;
        float m = -1e30f;
#pragma unroll
        for (int f = 0; f < FF; f++) m = fmaxf(m, lsm[h * 8 + f]);
        float e[FF];
        float ssum = 0.f;
#pragma unroll
        for (int f = 0; f < FF; f++) { e[f] = __expf(lsm[h * 8 + f] - m); ssum += e[f]; }
        float inv = 1.f / ssum;
#pragma unroll
        for (int f = 0; f < FF; f++) am[h * 8 + f] = e[f] * inv;
    }
    __syncthreads();

    if (write_attn && t < 96) {
        int h = t >> 3, f = t & 7;
        attn_out[(((size_t)b * HH + h) * SS + s) * FF + f] = am[t];
    }

    for (int c = t; c < CC; c += 256) {
        int h = c >> 6;
        float acc = 0.f;
#pragma unroll
        for (int f = 0; f < FF; f++) acc += am[h * 8 + f] * trs[f * CC + c];
        pre[((size_t)b * NTOK + 1 + s) * CC + c] = acc;
    }
}

// ---------------- host ----------------
extern "C" void kernel_launch(void* const* d_in, const int* in_sizes, int n_in,
                              void* d_out, int out_size)
{
    const float* x     = (const float*)d_in[0];
    const float* Wqkv  = (const float*)d_in[1];
    const float* Wpq   = (const float*)d_in[2];
    const float* Wpkv  = (const float*)d_in[3];
    const float* Wproj = (const float*)d_in[4];
    const float* bproj = (const float*)d_in[5];
    // d_in[6]=seq_len (196), d_in[7]=num_frames (8): fixed for this problem.

    float *qkv, *traj, *xd, *q2, *gb, *pre;
    cudaGetSymbolAddress((void**)&qkv,  g_qkv);
    cudaGetSymbolAddress((void**)&traj, g_traj);
    cudaGetSymbolAddress((void**)&xd,   g_xd);
    cudaGetSymbolAddress((void**)&q2,   g_q2v);
    cudaGetSymbolAddress((void**)&gb,   g_gb);
    cudaGetSymbolAddress((void**)&pre,  g_pre);

    const size_t OUT_MAIN = (size_t)BB * NTOK * CC;   // 2,409,984
    const size_t OUT_ATTN = (size_t)BB * HH * SS * FF; // 301,056
    int write_attn = ((size_t)out_size >= OUT_MAIN + OUT_ATTN) ? 1 : 0;
    float* attn_ptr = (float*)d_out + OUT_MAIN;

    const int spa_smem = SPA_SMEM_FLOATS * 4;
    const int p2_smem = P2_SMEM_FLOATS * 4;
    cudaFuncSetAttribute(spatial_kernel, cudaFuncAttributeMaxDynamicSharedMemorySize, spa_smem);
    cudaFuncSetAttribute(phase2_kernel,  cudaFuncAttributeMaxDynamicSharedMemorySize, p2_smem);

    // 1) qkv = x @ W_qkv : (3138 x 768) @ (768 x 2304)
    sgemm_kernel<<<dim3((3 * CC) / 128, (BB * NTOK + 127) / 128), 256>>>(
        x, Wqkv, qkv, BB * NTOK, 3 * CC, CC, 1.0f, nullptr);

    // 2) CLS attention -> pre[b, 0, :]
    cls_kernel<<<BB * HH, 256>>>(qkv, pre);

    // 3) fused spatial attention -> traj (B,S,F,C)
    spatial_kernel<<<dim3(SS / 32, FF, BB * HH), 128, spa_smem>>>(qkv, traj);

    // 4) x_diag gather
    {
        int tot = BB * SS * (CC / 4);
        xdiag_kernel<<<(tot + 255) / 256, 256>>>(traj, xd);
    }

    // 5) q2 = scale * x_diag @ W_pq : (3136 x 768) @ (768 x 768)
    sgemm_kernel<<<dim3(CC / 128, (BB * SS + 127) / 128), 256>>>(
        xd, Wpq, q2, BB * SS, CC, CC, SCALE, nullptr);

    // 6) g = per-head W_pk @ q2  (replaces the 29.6 GF k2 GEMM)
    g_kernel<<<dim3((BB * SS) / 64, CC / 64, HH), 256>>>(q2, Wpkv, gb);

    // 7) phase-2 attention: logits, softmax (-> attn output), weighted traj sum -> pre[b,1+s,:]
    phase2_kernel<<<BB * SS, 256, p2_smem>>>(traj, gb, pre, attn_ptr, write_attn);

    // 8) out = pre @ W_proj + b_proj -> d_out[0 .. B*N*C)
    sgemm_kernel<<<dim3(CC / 128, (BB * NTOK + 127) / 128), 256>>>(
        pre, Wproj, (float*)d_out, BB * NTOK, CC, CC, 1.0f, bproj);
}

// round 6
// speedup vs baseline: 1.3167x; 1.3167x over previous
#include <cuda_runtime.h>
#include <cstdint>
#include <cstddef>

#define BB 2
#define NTOK 1569
#define CC 768
#define HH 12
#define PP 196
#define FF 8
#define SS 1568
#define SCALE 0.125f

// ---------------- scratch (static device globals: no allocation) ----------------
__device__ float g_qkv[(size_t)BB * NTOK * 3 * CC];   // (B*N, 2304)
__device__ float g_traj[(size_t)BB * SS * FF * CC];   // (B,S,F,C)
__device__ float g_xd[(size_t)BB * SS * CC];          // x_diag (B,S,C)
__device__ float g_q2v[(size_t)BB * SS * CC];         // q2 (B,S,C) head-major, pre-scaled
__device__ float g_gb[(size_t)BB * SS * HH * CC];     // g (B,S,H,C)
__device__ float g_pre[(size_t)BB * NTOK * CC];       // concat(cls_out, out)

// =================== tf32 tensor-core SGEMM ===================
// C = alpha * A(MxK)@B(KxN) (+bias).  Requires N%128==0, K%32==0. M edge guarded.
// Block tile 128x128x32, 8 warps (4 in M x 2 in N), warp tile 32x64, mma m16n8k8.

__device__ __forceinline__ uint32_t f2tf32(float x) {
    uint32_t r;
    asm("cvt.rna.tf32.f32 %0, %1;" : "=r"(r) : "f"(x));
    return r;
}

__device__ __forceinline__ void mma_tf32(float* d, const uint32_t* a, const uint32_t* b) {
    asm volatile(
        "mma.sync.aligned.m16n8k8.row.col.f32.tf32.tf32.f32 "
        "{%0,%1,%2,%3}, {%4,%5,%6,%7}, {%8,%9}, {%0,%1,%2,%3};"
        : "+f"(d[0]), "+f"(d[1]), "+f"(d[2]), "+f"(d[3])
        : "r"(a[0]), "r"(a[1]), "r"(a[2]), "r"(a[3]), "r"(b[0]), "r"(b[1]));
}

#define ASTR 36   // A smem row stride (floats): 144B, 16B aligned, conflict-free frag reads
#define BSTR 136  // B smem row stride: 544B, 16B aligned, conflict-free frag reads

__global__ void __launch_bounds__(256, 2) sgemm_tf32_kernel(
    const float* __restrict__ A, const float* __restrict__ B, float* __restrict__ C,
    int M, int N, int K, float alpha, const float* __restrict__ bias)
{
    __shared__ uint32_t As[128 * ASTR];  // As[m][k]  (row-major, k contiguous)
    __shared__ uint32_t Bs[32 * BSTR];   // Bs[k][n]  (k-major, n contiguous)

    const int tid = threadIdx.x;
    const int lane = tid & 31;
    const int warp = tid >> 5;
    const int gid = lane >> 2;   // 0..7
    const int tig = lane & 3;    // 0..3
    const int warp_m = warp >> 1;          // 0..3  -> 32 rows each
    const int warp_n = warp & 1;           // 0..1  -> 64 cols each
    const int row0 = blockIdx.y * 128;
    const int col0 = blockIdx.x * 128;

    float acc[2][8][4];
#pragma unroll
    for (int mf = 0; mf < 2; mf++)
#pragma unroll
        for (int nf = 0; nf < 8; nf++)
#pragma unroll
            for (int c = 0; c < 4; c++) acc[mf][nf][c] = 0.f;

    // A copy mapping: 1024 float4 tasks (128 rows x 8 quads), 4 per thread
    // idx -> row = idx>>3, quad = idx&7  (warp covers 4 rows x 128B: coalesced)
    // B copy mapping: 1024 float4 tasks (32 k x 32 quads) (warp covers 1 row x 512B)
    const int nkt = K >> 5;

    for (int kt = 0; kt < nkt; kt++) {
        const int k0 = kt << 5;
#pragma unroll
        for (int r = 0; r < 4; r++) {
            int idx = tid + (r << 8);
            int row_l = idx >> 3;
            int kq = (idx & 7) << 2;
            int grow = row0 + row_l;
            float4 v = make_float4(0.f, 0.f, 0.f, 0.f);
            if (grow < M)
                v = *(const float4*)(A + (size_t)grow * K + k0 + kq);
            uint32_t* dst = As + row_l * ASTR + kq;
            dst[0] = f2tf32(v.x); dst[1] = f2tf32(v.y);
            dst[2] = f2tf32(v.z); dst[3] = f2tf32(v.w);
        }
#pragma unroll
        for (int r = 0; r < 4; r++) {
            int idx = tid + (r << 8);
            int k_l = idx >> 5;
            int nq = (idx & 31) << 2;
            float4 v = *(const float4*)(B + (size_t)(k0 + k_l) * N + col0 + nq);
            uint32_t* dst = Bs + k_l * BSTR + nq;
            dst[0] = f2tf32(v.x); dst[1] = f2tf32(v.y);
            dst[2] = f2tf32(v.z); dst[3] = f2tf32(v.w);
        }
        __syncthreads();

#pragma unroll
        for (int s = 0; s < 4; s++) {           // four k8 steps
            uint32_t a[2][4];
#pragma unroll
            for (int mf = 0; mf < 2; mf++) {
                int mb = warp_m * 32 + mf * 16;
                const uint32_t* ap = As + (mb + gid) * ASTR + s * 8 + tig;
                a[mf][0] = ap[0];
                a[mf][1] = ap[8 * ASTR];
                a[mf][2] = ap[4];
                a[mf][3] = ap[8 * ASTR + 4];
            }
            uint32_t b[8][2];
#pragma unroll
            for (int nf = 0; nf < 8; nf++) {
                int nb = warp_n * 64 + nf * 8 + gid;
                b[nf][0] = Bs[(s * 8 + tig) * BSTR + nb];
                b[nf][1] = Bs[(s * 8 + tig + 4) * BSTR + nb];
            }
#pragma unroll
            for (int mf = 0; mf < 2; mf++)
#pragma unroll
                for (int nf = 0; nf < 8; nf++)
                    mma_tf32(acc[mf][nf], a[mf], b[nf]);
        }
        __syncthreads();
    }

    // epilogue
#pragma unroll
    for (int mf = 0; mf < 2; mf++) {
        int rbase = row0 + warp_m * 32 + mf * 16 + gid;
#pragma unroll
        for (int half = 0; half < 2; half++) {
            int r = rbase + half * 8;
            if (r >= M) continue;
#pragma unroll
            for (int nf = 0; nf < 8; nf++) {
                int cidx = col0 + warp_n * 64 + nf * 8 + tig * 2;
                float2 v;
                v.x = acc[mf][nf][half * 2 + 0] * alpha;
                v.y = acc[mf][nf][half * 2 + 1] * alpha;
                if (bias) { v.x += bias[cidx]; v.y += bias[cidx + 1]; }
                *(float2*)(C + (size_t)r * N + cidx) = v;
            }
        }
    }
}

// ---------------- CLS attention: one block per (b,h) ----------------
__global__ void __launch_bounds__(256) cls_kernel(const float* __restrict__ qkv,
                                                  float* __restrict__ pre)
{
    __shared__ float qv[64];
    __shared__ float logit[NTOK];
    __shared__ float red[256];
    const int bh = blockIdx.x;
    const int b = bh / HH, h = bh % HH;
    const int t = threadIdx.x;
    const float* base = qkv + (size_t)b * NTOK * (3 * CC);

    if (t < 64) qv[t] = base[h * 64 + t] * SCALE;
    __syncthreads();

    for (int n = t; n < NTOK; n += 256) {
        const float* kr = base + (size_t)n * (3 * CC) + CC + h * 64;
        float s = 0.f;
#pragma unroll 16
        for (int dd = 0; dd < 64; dd++) s += qv[dd] * kr[dd];
        logit[n] = s;
    }
    __syncthreads();

    float m = -1e30f;
    for (int n = t; n < NTOK; n += 256) m = fmaxf(m, logit[n]);
    red[t] = m; __syncthreads();
    for (int s2 = 128; s2 > 0; s2 >>= 1) {
        if (t < s2) red[t] = fmaxf(red[t], red[t + s2]);
        __syncthreads();
    }
    const float mx = red[0];
    __syncthreads();

    float ssum = 0.f;
    for (int n = t; n < NTOK; n += 256) {
        float e = __expf(logit[n] - mx);
        logit[n] = e;
        ssum += e;
    }
    red[t] = ssum; __syncthreads();
    for (int s2 = 128; s2 > 0; s2 >>= 1) {
        if (t < s2) red[t] += red[t + s2];
        __syncthreads();
    }
    const float inv = 1.f / red[0];
    __syncthreads();

    const int dd = t & 63, grp = t >> 6;
    float acc = 0.f;
    for (int n = grp; n < NTOK; n += 4)
        acc += logit[n] * base[(size_t)n * (3 * CC) + 2 * CC + h * 64 + dd];
    red[t] = acc; __syncthreads();
    if (t < 64) {
        float v = red[t] + red[t + 64] + red[t + 128] + red[t + 192];
        pre[(size_t)b * NTOK * CC + h * 64 + t] = v * inv;
    }
}

// ---------------- fused per-frame spatial attention ----------------
#define SPA_SMEM_FLOATS (2048 + 32 * 197 + 64 * 197)
__global__ void __launch_bounds__(128) spatial_kernel(const float* __restrict__ qkv,
                                                      float* __restrict__ traj)
{
    extern __shared__ float sm[];
    float* qs = sm;                       // 2048 : qs[dd*32 + q], pre-scaled
    float* ls = sm + 2048;                // 32*197
    float* kv = sm + 2048 + 32 * 197;     // 64*197

    const int t = threadIdx.x;
    const int bh = blockIdx.z;
    const int b = bh / HH, h = bh % HH;
    const int f = blockIdx.y;
    const int q0 = blockIdx.x * 32;
    const float* base = qkv + (size_t)b * NTOK * (3 * CC);

    for (int idx = t; idx < 512; idx += 128) {
        int q = idx >> 4;
        int dv = (idx & 15) * 4;
        float4 v = *(const float4*)(base + (size_t)(1 + q0 + q) * (3 * CC) + h * 64 + dv);
        qs[(dv + 0) * 32 + q] = v.x * SCALE;
        qs[(dv + 1) * 32 + q] = v.y * SCALE;
        qs[(dv + 2) * 32 + q] = v.z * SCALE;
        qs[(dv + 3) * 32 + q] = v.w * SCALE;
    }
    for (int idx = t; idx < PP * 16; idx += 128) {
        int n = idx >> 4;
        int dv = (idx & 15) * 4;
        float4 v = *(const float4*)(base + (size_t)(1 + f * PP + n) * (3 * CC) + CC + h * 64 + dv);
        kv[(dv + 0) * 197 + n] = v.x;
        kv[(dv + 1) * 197 + n] = v.y;
        kv[(dv + 2) * 197 + n] = v.z;
        kv[(dv + 3) * 197 + n] = v.w;
    }
    __syncthreads();

    {
        const int tx = t & 31, ty = t >> 5;
        float acc[8][7];
#pragma unroll
        for (int i = 0; i < 8; i++)
#pragma unroll
            for (int j = 0; j < 7; j++) acc[i][j] = 0.f;
#pragma unroll 4
        for (int kk = 0; kk < 64; kk++) {
            float a[8];
#pragma unroll
            for (int i = 0; i < 8; i++) a[i] = qs[kk * 32 + ty * 8 + i];
#pragma unroll
            for (int j = 0; j < 6; j++) {
                float bv = kv[kk * 197 + tx + 32 * j];
#pragma unroll
                for (int i = 0; i < 8; i++) acc[i][j] += a[i] * bv;
            }
            if (tx < 4) {
                float bv = kv[kk * 197 + tx + 192];
#pragma unroll
                for (int i = 0; i < 8; i++) acc[i][6] += a[i] * bv;
            }
        }
#pragma unroll
        for (int i = 0; i < 8; i++) {
#pragma unroll
            for (int j = 0; j < 6; j++)
                ls[(ty * 8 + i) * 197 + tx + 32 * j] = acc[i][j];
            if (tx < 4) ls[(ty * 8 + i) * 197 + tx + 192] = acc[i][6];
        }
    }
    __syncthreads();

    {
        const int lane = t & 31, w = t >> 5;
        for (int qq = w * 8; qq < w * 8 + 8; qq++) {
            float* row = ls + qq * 197;
            float m = -1e30f;
            for (int n = lane; n < PP; n += 32) m = fmaxf(m, row[n]);
#pragma unroll
            for (int o = 16; o; o >>= 1) m = fmaxf(m, __shfl_xor_sync(0xffffffffu, m, o));
            float s = 0.f;
            for (int n = lane; n < PP; n += 32) {
                float e = __expf(row[n] - m);
                row[n] = e;
                s += e;
            }
#pragma unroll
            for (int o = 16; o; o >>= 1) s += __shfl_xor_sync(0xffffffffu, s, o);
            float inv = 1.f / s;
            for (int n = lane; n < PP; n += 32) row[n] *= inv;
        }
    }
    __syncthreads();

    for (int idx = t; idx < PP * 16; idx += 128) {
        int n = idx >> 4;
        int dv = (idx & 15) * 4;
        *(float4*)(kv + n * 64 + dv) =
            *(const float4*)(base + (size_t)(1 + f * PP + n) * (3 * CC) + 2 * CC + h * 64 + dv);
    }
    __syncthreads();

    {
        const int tx2 = t & 15, ty2 = t >> 4;
        float acc[4][4];
#pragma unroll
        for (int i = 0; i < 4; i++)
#pragma unroll
            for (int j = 0; j < 4; j++) acc[i][j] = 0.f;
        for (int n = 0; n < PP; n++) {
            float a[4];
#pragma unroll
            for (int i = 0; i < 4; i++) a[i] = ls[(ty2 * 4 + i) * 197 + n];
            float4 bv = *(float4*)(kv + n * 64 + tx2 * 4);
#pragma unroll
            for (int i = 0; i < 4; i++) {
                acc[i][0] += a[i] * bv.x;
                acc[i][1] += a[i] * bv.y;
                acc[i][2] += a[i] * bv.z;
                acc[i][3] += a[i] * bv.w;
            }
        }
#pragma unroll
        for (int i = 0; i < 4; i++) {
            int s = q0 + ty2 * 4 + i;
            float4 o = make_float4(acc[i][0], acc[i][1], acc[i][2], acc[i][3]);
            *(float4*)(traj + (((size_t)(b * SS + s) * FF + f) * CC + h * 64 + tx2 * 4)) = o;
        }
    }
}

// ---------------- x_diag gather ----------------
__global__ void xdiag_kernel(const float* __restrict__ traj, float* __restrict__ xd)
{
    int i = blockIdx.x * blockDim.x + threadIdx.x;
    const int TOT = BB * SS * (CC / 4);
    if (i >= TOT) return;
    int bs = i / (CC / 4);
    int c4 = i - bs * (CC / 4);
    int s = bs % SS;
    int f = s / PP;
    ((float4*)xd)[(size_t)bs * (CC / 4) + c4] =
        ((const float4*)traj)[((size_t)bs * FF + f) * (CC / 4) + c4];
}

// ---------------- g[b,s,h,c] = sum_d q2[bs, h*64+d] * W_pkv[c, h*64+d] ----------------
__global__ void __launch_bounds__(256) g_kernel(
    const float* __restrict__ q2, const float* __restrict__ Wpkv, float* __restrict__ g)
{
    __shared__ float As[64 * 65];
    __shared__ float Bs[64 * 65];
    const int t = threadIdx.x;
    const int m0 = blockIdx.x * 64;
    const int n0 = blockIdx.y * 64;
    const int h = blockIdx.z;

#pragma unroll
    for (int r = 0; r < 4; r++) {
        int idx = t + r * 256;
        int mm = idx >> 4;
        int dv = (idx & 15) * 4;
        float4 a = *(const float4*)(q2 + (size_t)(m0 + mm) * CC + h * 64 + dv);
        As[mm * 65 + dv + 0] = a.x;
        As[mm * 65 + dv + 1] = a.y;
        As[mm * 65 + dv + 2] = a.z;
        As[mm * 65 + dv + 3] = a.w;
        float4 bv = *(const float4*)(Wpkv + (size_t)(n0 + mm) * (2 * CC) + h * 64 + dv);
        Bs[mm * 65 + dv + 0] = bv.x;
        Bs[mm * 65 + dv + 1] = bv.y;
        Bs[mm * 65 + dv + 2] = bv.z;
        Bs[mm * 65 + dv + 3] = bv.w;
    }
    __syncthreads();

    const int tx = t & 15, ty = t >> 4;
    float acc[4][4];
#pragma unroll
    for (int i = 0; i < 4; i++)
#pragma unroll
        for (int j = 0; j < 4; j++) acc[i][j] = 0.f;
#pragma unroll 8
    for (int kk = 0; kk < 64; kk++) {
        float a[4], b[4];
#pragma unroll
        for (int i = 0; i < 4; i++) a[i] = As[(ty * 4 + i) * 65 + kk];
#pragma unroll
        for (int j = 0; j < 4; j++) b[j] = Bs[(tx * 4 + j) * 65 + kk];
#pragma unroll
        for (int i = 0; i < 4; i++)
#pragma unroll
            for (int j = 0; j < 4; j++) acc[i][j] += a[i] * b[j];
    }
#pragma unroll
    for (int i = 0; i < 4; i++) {
        float4 v = make_float4(acc[i][0], acc[i][1], acc[i][2], acc[i][3]);
        *(float4*)(g + ((size_t)(m0 + ty * 4 + i) * HH + h) * CC + n0 + tx * 4) = v;
    }
}

// ---------------- phase-2: logits + softmax + output + attn write ----------------
#define P2_SMEM_FLOATS (FF * CC + HH * CC + 96 + 96)
__global__ void __launch_bounds__(256) phase2_kernel(
    const float* __restrict__ traj, const float* __restrict__ g,
    float* __restrict__ pre, float* __restrict__ attn_out, int write_attn)
{
    extern __shared__ float sm[];
    float* trs = sm;
    float* gs = sm + FF * CC;
    float* lsm = gs + HH * CC;
    float* am = lsm + 96;

    const int bs = blockIdx.x;
    const int b = bs / SS, s = bs % SS;
    const int t = threadIdx.x;

    const float* tr = traj + (size_t)bs * FF * CC;
    for (int i = t; i < FF * CC / 4; i += 256)
        ((float4*)trs)[i] = ((const float4*)tr)[i];
    const float* gg = g + (size_t)bs * HH * CC;
    for (int i = t; i < HH * CC / 4; i += 256)
        ((float4*)gs)[i] = ((const float4*)gg)[i];
    __syncthreads();

    {
        const int lane = t & 31, w = t >> 5;
        for (int p = w * 12; p < w * 12 + 12; p++) {
            int h = p >> 3, f = p & 7;
            float ssum = 0.f;
            for (int c = lane; c < CC; c += 32)
                ssum += trs[f * CC + c] * gs[h * CC + c];
#pragma unroll
            for (int o = 16; o; o >>= 1) ssum += __shfl_xor_sync(0xffffffffu, ssum, o);
            if (lane == 0) lsm[p] = ssum;
        }
    }
    __syncthreads();

    if (t < HH) {
        int h = t;
        float m = -1e30f;
#pragma unroll
        for (int f = 0; f < FF; f++) m = fmaxf(m, lsm[h * 8 + f]);
        float e[FF];
        float ssum = 0.f;
#pragma unroll
        for (int f = 0; f < FF; f++) { e[f] = __expf(lsm[h * 8 + f] - m); ssum += e[f]; }
        float inv = 1.f / ssum;
#pragma unroll
        for (int f = 0; f < FF; f++) am[h * 8 + f] = e[f] * inv;
    }
    __syncthreads();

    if (write_attn && t < 96) {
        int h = t >> 3, f = t & 7;
        attn_out[(((size_t)b * HH + h) * SS + s) * FF + f] = am[t];
    }

    for (int c = t; c < CC; c += 256) {
        int h = c >> 6;
        float acc = 0.f;
#pragma unroll
        for (int f = 0; f < FF; f++) acc += am[h * 8 + f] * trs[f * CC + c];
        pre[((size_t)b * NTOK + 1 + s) * CC + c] = acc;
    }
}

// ---------------- host ----------------
extern "C" void kernel_launch(void* const* d_in, const int* in_sizes, int n_in,
                              void* d_out, int out_size)
{
    const float* x     = (const float*)d_in[0];
    const float* Wqkv  = (const float*)d_in[1];
    const float* Wpq   = (const float*)d_in[2];
    const float* Wpkv  = (const float*)d_in[3];
    const float* Wproj = (const float*)d_in[4];
    const float* bproj = (const float*)d_in[5];

    float *qkv, *traj, *xd, *q2, *gb, *pre;
    cudaGetSymbolAddress((void**)&qkv,  g_qkv);
    cudaGetSymbolAddress((void**)&traj, g_traj);
    cudaGetSymbolAddress((void**)&xd,   g_xd);
    cudaGetSymbolAddress((void**)&q2,   g_q2v);
    cudaGetSymbolAddress((void**)&gb,   g_gb);
    cudaGetSymbolAddress((void**)&pre,  g_pre);

    const size_t OUT_MAIN = (size_t)BB * NTOK * CC;
    const size_t OUT_ATTN = (size_t)BB * HH * SS * FF;
    int write_attn = ((size_t)out_size >= OUT_MAIN + OUT_ATTN) ? 1 : 0;
    float* attn_ptr = (float*)d_out + OUT_MAIN;

    const int spa_smem = SPA_SMEM_FLOATS * 4;
    const int p2_smem = P2_SMEM_FLOATS * 4;
    cudaFuncSetAttribute(spatial_kernel, cudaFuncAttributeMaxDynamicSharedMemorySize, spa_smem);
    cudaFuncSetAttribute(phase2_kernel,  cudaFuncAttributeMaxDynamicSharedMemorySize, p2_smem);

    // 1) qkv = x @ W_qkv : (3138 x 2304 x 768)  [tf32 tensor cores]
    sgemm_tf32_kernel<<<dim3((3 * CC) / 128, (BB * NTOK + 127) / 128), 256>>>(
        x, Wqkv, qkv, BB * NTOK, 3 * CC, CC, 1.0f, nullptr);

    // 2) CLS attention -> pre[b, 0, :]
    cls_kernel<<<BB * HH, 256>>>(qkv, pre);

    // 3) fused spatial attention -> traj (B,S,F,C)
    spatial_kernel<<<dim3(SS / 32, FF, BB * HH), 128, spa_smem>>>(qkv, traj);

    // 4) x_diag gather
    {
        int tot = BB * SS * (CC / 4);
        xdiag_kernel<<<(tot + 255) / 256, 256>>>(traj, xd);
    }

    // 5) q2 = scale * x_diag @ W_pq  [tf32 tensor cores]
    sgemm_tf32_kernel<<<dim3(CC / 128, (BB * SS + 127) / 128), 256>>>(
        xd, Wpq, q2, BB * SS, CC, CC, SCALE, nullptr);

    // 6) g = per-head W_pk @ q2  (replaces the 29.6 GF k2 GEMM)
    g_kernel<<<dim3((BB * SS) / 64, CC / 64, HH), 256>>>(q2, Wpkv, gb);

    // 7) phase-2 attention
    phase2_kernel<<<BB * SS, 256, p2_smem>>>(traj, gb, pre, attn_ptr, write_attn);

    // 8) out = pre @ W_proj + b_proj  [tf32 tensor cores]
    sgemm_tf32_kernel<<<dim3(CC / 128, (BB * NTOK + 127) / 128), 256>>>(
        pre, Wproj, (float*)d_out, BB * NTOK, CC, CC, 1.0f, bproj);
}

// round 7
// speedup vs baseline: 1.5879x; 1.2059x over previous
#include <cuda_runtime.h>
#include <cstdint>
#include <cstddef>

#define BB 2
#define NTOK 1569
#define CC 768
#define HH 12
#define PP 196
#define FF 8
#define SS 1568
#define SCALE 0.125f

// ---------------- scratch (static device globals: no allocation) ----------------
__device__ float g_qkv[(size_t)BB * NTOK * 3 * CC];   // (B*N, 2304)
__device__ float g_traj[(size_t)BB * SS * FF * CC];   // (B,S,F,C)
__device__ float g_xd[(size_t)BB * SS * CC];          // x_diag (B,S,C)
__device__ float g_q2v[(size_t)BB * SS * CC];         // q2 (B,S,C), pre-scaled
__device__ float g_gb[(size_t)BB * SS * HH * CC];     // g (B,S,H,C)
__device__ float g_pre[(size_t)BB * NTOK * CC];       // concat(cls_out, out)

// =================== tf32 helpers ===================
__device__ __forceinline__ uint32_t f2tf32(float x) {
    uint32_t r;
    asm("cvt.rna.tf32.f32 %0, %1;" : "=r"(r) : "f"(x));
    return r;
}

__device__ __forceinline__ void mma_tf32(float* d, const uint32_t* a, const uint32_t* b) {
    asm volatile(
        "mma.sync.aligned.m16n8k8.row.col.f32.tf32.tf32.f32 "
        "{%0,%1,%2,%3}, {%4,%5,%6,%7}, {%8,%9}, {%0,%1,%2,%3};"
        : "+f"(d[0]), "+f"(d[1]), "+f"(d[2]), "+f"(d[3])
        : "r"(a[0]), "r"(a[1]), "r"(a[2]), "r"(a[3]), "r"(b[0]), "r"(b[1]));
}

// =================== tf32 tensor-core SGEMM ===================
// C = alpha * A(MxK)@B(KxN) (+bias).  N%128==0, K%32==0, M edge guarded.
#define ASTR 36
#define BSTR 136

__global__ void __launch_bounds__(256, 2) sgemm_tf32_kernel(
    const float* __restrict__ A, const float* __restrict__ B, float* __restrict__ C,
    int M, int N, int K, float alpha, const float* __restrict__ bias)
{
    __shared__ uint32_t As[128 * ASTR];
    __shared__ uint32_t Bs[32 * BSTR];

    const int tid = threadIdx.x;
    const int lane = tid & 31;
    const int warp = tid >> 5;
    const int gid = lane >> 2;
    const int tig = lane & 3;
    const int warp_m = warp >> 1;
    const int warp_n = warp & 1;
    const int row0 = blockIdx.y * 128;
    const int col0 = blockIdx.x * 128;

    float acc[2][8][4];
#pragma unroll
    for (int mf = 0; mf < 2; mf++)
#pragma unroll
        for (int nf = 0; nf < 8; nf++)
#pragma unroll
            for (int c = 0; c < 4; c++) acc[mf][nf][c] = 0.f;

    const int nkt = K >> 5;
    for (int kt = 0; kt < nkt; kt++) {
        const int k0 = kt << 5;
#pragma unroll
        for (int r = 0; r < 4; r++) {
            int idx = tid + (r << 8);
            int row_l = idx >> 3;
            int kq = (idx & 7) << 2;
            int grow = row0 + row_l;
            float4 v = make_float4(0.f, 0.f, 0.f, 0.f);
            if (grow < M)
                v = *(const float4*)(A + (size_t)grow * K + k0 + kq);
            uint32_t* dst = As + row_l * ASTR + kq;
            dst[0] = f2tf32(v.x); dst[1] = f2tf32(v.y);
            dst[2] = f2tf32(v.z); dst[3] = f2tf32(v.w);
        }
#pragma unroll
        for (int r = 0; r < 4; r++) {
            int idx = tid + (r << 8);
            int k_l = idx >> 5;
            int nq = (idx & 31) << 2;
            float4 v = *(const float4*)(B + (size_t)(k0 + k_l) * N + col0 + nq);
            uint32_t* dst = Bs + k_l * BSTR + nq;
            dst[0] = f2tf32(v.x); dst[1] = f2tf32(v.y);
            dst[2] = f2tf32(v.z); dst[3] = f2tf32(v.w);
        }
        __syncthreads();

#pragma unroll
        for (int s = 0; s < 4; s++) {
            uint32_t a[2][4];
#pragma unroll
            for (int mf = 0; mf < 2; mf++) {
                int mb = warp_m * 32 + mf * 16;
                const uint32_t* ap = As + (mb + gid) * ASTR + s * 8 + tig;
                a[mf][0] = ap[0];
                a[mf][1] = ap[8 * ASTR];
                a[mf][2] = ap[4];
                a[mf][3] = ap[8 * ASTR + 4];
            }
            uint32_t b[8][2];
#pragma unroll
            for (int nf = 0; nf < 8; nf++) {
                int nb = warp_n * 64 + nf * 8 + gid;
                b[nf][0] = Bs[(s * 8 + tig) * BSTR + nb];
                b[nf][1] = Bs[(s * 8 + tig + 4) * BSTR + nb];
            }
#pragma unroll
            for (int mf = 0; mf < 2; mf++)
#pragma unroll
                for (int nf = 0; nf < 8; nf++)
                    mma_tf32(acc[mf][nf], a[mf], b[nf]);
        }
        __syncthreads();
    }

#pragma unroll
    for (int mf = 0; mf < 2; mf++) {
        int rbase = row0 + warp_m * 32 + mf * 16 + gid;
#pragma unroll
        for (int half = 0; half < 2; half++) {
            int r = rbase + half * 8;
            if (r >= M) continue;
#pragma unroll
            for (int nf = 0; nf < 8; nf++) {
                int cidx = col0 + warp_n * 64 + nf * 8 + tig * 2;
                float2 v;
                v.x = acc[mf][nf][half * 2 + 0] * alpha;
                v.y = acc[mf][nf][half * 2 + 1] * alpha;
                if (bias) { v.x += bias[cidx]; v.y += bias[cidx + 1]; }
                *(float2*)(C + (size_t)r * N + cidx) = v;
            }
        }
    }
}

// ---------------- CLS attention: one block per (b,h) ----------------
__global__ void __launch_bounds__(256) cls_kernel(const float* __restrict__ qkv,
                                                  float* __restrict__ pre)
{
    __shared__ float qv[64];
    __shared__ float logit[NTOK];
    __shared__ float red[256];
    const int bh = blockIdx.x;
    const int b = bh / HH, h = bh % HH;
    const int t = threadIdx.x;
    const float* base = qkv + (size_t)b * NTOK * (3 * CC);

    if (t < 64) qv[t] = base[h * 64 + t] * SCALE;
    __syncthreads();

    for (int n = t; n < NTOK; n += 256) {
        const float* kr = base + (size_t)n * (3 * CC) + CC + h * 64;
        float s = 0.f;
#pragma unroll 16
        for (int dd = 0; dd < 64; dd++) s += qv[dd] * kr[dd];
        logit[n] = s;
    }
    __syncthreads();

    float m = -1e30f;
    for (int n = t; n < NTOK; n += 256) m = fmaxf(m, logit[n]);
    red[t] = m; __syncthreads();
    for (int s2 = 128; s2 > 0; s2 >>= 1) {
        if (t < s2) red[t] = fmaxf(red[t], red[t + s2]);
        __syncthreads();
    }
    const float mx = red[0];
    __syncthreads();

    float ssum = 0.f;
    for (int n = t; n < NTOK; n += 256) {
        float e = __expf(logit[n] - mx);
        logit[n] = e;
        ssum += e;
    }
    red[t] = ssum; __syncthreads();
    for (int s2 = 128; s2 > 0; s2 >>= 1) {
        if (t < s2) red[t] += red[t + s2];
        __syncthreads();
    }
    const float inv = 1.f / red[0];
    __syncthreads();

    const int dd = t & 63, grp = t >> 6;
    float acc = 0.f;
    for (int n = grp; n < NTOK; n += 4)
        acc += logit[n] * base[(size_t)n * (3 * CC) + 2 * CC + h * 64 + dd];
    red[t] = acc; __syncthreads();
    if (t < 64) {
        float v = red[t] + red[t + 64] + red[t + 128] + red[t + 192];
        pre[(size_t)b * NTOK * CC + h * 64 + t] = v * inv;
    }
}

// ---------------- tf32 tensor-core spatial attention ----------------
// grid (49, B*H), 128 threads, f-loop inside. Per block: 32 queries, all 8 frames.
// smem: qs[32][QSTR] tf32 | ls[32][LSTR] fp32 logits -> tf32 probs | pool (K then V)
#define QT 32
#define NPAD 208
#define QSTR 68   // banks gid*4+tig : conflict-free A frags
#define KSTR 216  // banks tig*24+gid: conflict-free B frags
#define LSTR 212  // banks gid*20+tig: conflict-free A frags (PV)
#define VSTR 72   // banks tig*8+gid : conflict-free B frags (PV)
#define SPA2_POOL 14976                 // max(64*KSTR=13824, 208*VSTR=14976)
#define SPA2_SMEM_FLOATS (QT*QSTR + QT*LSTR + SPA2_POOL)

__global__ void __launch_bounds__(128, 2) spatial_tc_kernel(const float* __restrict__ qkv,
                                                            float* __restrict__ traj)
{
    extern __shared__ float sm[];
    uint32_t* qs = (uint32_t*)sm;               // [QT][QSTR]
    float* ls = sm + QT * QSTR;                 // [QT][LSTR]
    uint32_t* ks = (uint32_t*)(ls + QT * LSTR); // [64][KSTR]
    uint32_t* vs = ks;                          // [NPAD][VSTR] (reused)

    const int t = threadIdx.x;
    const int lane = t & 31, warp = t >> 5;
    const int gid = lane >> 2, tig = lane & 3;
    const int warp_m = warp >> 1;   // 0..1
    const int warp_n = warp & 1;    // 0..1
    const int bh = blockIdx.y;
    const int b = bh / HH, h = bh % HH;
    const int q0 = blockIdx.x * QT;                  // 49*32 = 1568 exact
    const float* base = qkv + (size_t)b * NTOK * (3 * CC);

    // Q tile: [q][d] row-major tf32, pre-scaled
#pragma unroll
    for (int r = 0; r < 4; r++) {
        int idx = t + r * 128;            // 512 float4 tasks
        int q = idx >> 4, dv = (idx & 15) << 2;
        float4 v = *(const float4*)(base + (size_t)(1 + q0 + q) * (3 * CC) + h * 64 + dv);
        uint32_t* dst = qs + q * QSTR + dv;
        dst[0] = f2tf32(v.x * SCALE); dst[1] = f2tf32(v.y * SCALE);
        dst[2] = f2tf32(v.z * SCALE); dst[3] = f2tf32(v.w * SCALE);
    }

    for (int f = 0; f < FF; f++) {
        // ---- K load (transposed [d][n]) + zero pads n=196..207 ----
        for (int idx = t; idx < PP * 16; idx += 128) {
            int n = idx >> 4, dv = (idx & 15) << 2;
            float4 v = *(const float4*)(base + (size_t)(1 + f * PP + n) * (3 * CC) + CC + h * 64 + dv);
            ks[(dv + 0) * KSTR + n] = f2tf32(v.x);
            ks[(dv + 1) * KSTR + n] = f2tf32(v.y);
            ks[(dv + 2) * KSTR + n] = f2tf32(v.z);
            ks[(dv + 3) * KSTR + n] = f2tf32(v.w);
        }
        for (int i = t; i < 64 * 12; i += 128) {
            int d = i / 12, n = 196 + (i % 12);
            ks[d * KSTR + n] = 0u;
        }
        __syncthreads();

        // ---- QK mma: M=32 (2 warps x m16), N=208 (2 warps x 104 = 13 n-frags), K=64 ----
        {
            float acc[13][4];
#pragma unroll
            for (int nf = 0; nf < 13; nf++)
#pragma unroll
                for (int c = 0; c < 4; c++) acc[nf][c] = 0.f;
#pragma unroll
            for (int s = 0; s < 8; s++) {
                uint32_t a[4];
                const uint32_t* ap = qs + (warp_m * 16 + gid) * QSTR + s * 8 + tig;
                a[0] = ap[0];
                a[1] = ap[8 * QSTR];
                a[2] = ap[4];
                a[3] = ap[8 * QSTR + 4];
#pragma unroll
                for (int nf = 0; nf < 13; nf++) {
                    int nb = warp_n * 104 + nf * 8 + gid;
                    uint32_t bfr[2];
                    bfr[0] = ks[(s * 8 + tig) * KSTR + nb];
                    bfr[1] = ks[(s * 8 + tig + 4) * KSTR + nb];
                    mma_tf32(acc[nf], a, bfr);
                }
            }
            // store logits to ls
#pragma unroll
            for (int nf = 0; nf < 13; nf++) {
                int col = warp_n * 104 + nf * 8 + tig * 2;
                int row = warp_m * 16 + gid;
                *(float2*)(ls + row * LSTR + col) = make_float2(acc[nf][0], acc[nf][1]);
                *(float2*)(ls + (row + 8) * LSTR + col) = make_float2(acc[nf][2], acc[nf][3]);
            }
        }
        __syncthreads();

        // ---- V load (overwrites K pool; safe after sync) ----
        for (int idx = t; idx < PP * 16; idx += 128) {
            int n = idx >> 4, dv = (idx & 15) << 2;
            float4 v = *(const float4*)(base + (size_t)(1 + f * PP + n) * (3 * CC) + 2 * CC + h * 64 + dv);
            uint32_t* dst = vs + n * VSTR + dv;
            dst[0] = f2tf32(v.x); dst[1] = f2tf32(v.y);
            dst[2] = f2tf32(v.z); dst[3] = f2tf32(v.w);
        }

        // ---- softmax per row (8 rows per warp); write probs as tf32; zero pads ----
        for (int i = 0; i < 8; i++) {
            int qq = warp * 8 + i;
            float* row = ls + qq * LSTR;
            float m = -1e30f;
            for (int n = lane; n < PP; n += 32) m = fmaxf(m, row[n]);
#pragma unroll
            for (int o = 16; o; o >>= 1) m = fmaxf(m, __shfl_xor_sync(0xffffffffu, m, o));
            float ssum = 0.f;
            float ev[7];
            int cnt = 0;
            for (int n = lane; n < PP; n += 32) {
                float e = __expf(row[n] - m);
                ev[cnt++] = e;
                ssum += e;
            }
#pragma unroll
            for (int o = 16; o; o >>= 1) ssum += __shfl_xor_sync(0xffffffffu, ssum, o);
            float inv = 1.f / ssum;
            cnt = 0;
            for (int n = lane; n < PP; n += 32)
                ((uint32_t*)row)[n] = f2tf32(ev[cnt++] * inv);
            if (lane < 12) ((uint32_t*)row)[196 + lane] = 0u;
        }
        __syncthreads();

        // ---- PV mma: M=32 (2 x m16), N=64 (2 x 32 = 4 n-frags), K=208 (26 steps) ----
        {
            float acc[4][4];
#pragma unroll
            for (int nf = 0; nf < 4; nf++)
#pragma unroll
                for (int c = 0; c < 4; c++) acc[nf][c] = 0.f;
            const uint32_t* lsu = (const uint32_t*)ls;
#pragma unroll
            for (int s = 0; s < 26; s++) {
                uint32_t a[4];
                const uint32_t* ap = lsu + (warp_m * 16 + gid) * LSTR + s * 8 + tig;
                a[0] = ap[0];
                a[1] = ap[8 * LSTR];
                a[2] = ap[4];
                a[3] = ap[8 * LSTR + 4];
#pragma unroll
                for (int nf = 0; nf < 4; nf++) {
                    int nb = warp_n * 32 + nf * 8 + gid;
                    uint32_t bfr[2];
                    bfr[0] = vs[(s * 8 + tig) * VSTR + nb];
                    bfr[1] = vs[(s * 8 + tig + 4) * VSTR + nb];
                    mma_tf32(acc[nf], a, bfr);
                }
            }
            // epilogue -> traj
#pragma unroll
            for (int half = 0; half < 2; half++) {
                int q = q0 + warp_m * 16 + gid + half * 8;
                float* orow = traj + (((size_t)(b * SS + q) * FF + f) * CC + h * 64);
#pragma unroll
                for (int nf = 0; nf < 4; nf++) {
                    int col = warp_n * 32 + nf * 8 + tig * 2;
                    *(float2*)(orow + col) =
                        make_float2(acc[nf][half * 2 + 0], acc[nf][half * 2 + 1]);
                }
            }
        }
        __syncthreads();
    }
}

// ---------------- x_diag gather ----------------
__global__ void xdiag_kernel(const float* __restrict__ traj, float* __restrict__ xd)
{
    int i = blockIdx.x * blockDim.x + threadIdx.x;
    const int TOT = BB * SS * (CC / 4);
    if (i >= TOT) return;
    int bs = i / (CC / 4);
    int c4 = i - bs * (CC / 4);
    int s = bs % SS;
    int f = s / PP;
    ((float4*)xd)[(size_t)bs * (CC / 4) + c4] =
        ((const float4*)traj)[((size_t)bs * FF + f) * (CC / 4) + c4];
}

// ---------------- g[b,s,h,c] = sum_d q2[bs, h*64+d] * W_pkv[c, h*64+d] ----------------
__global__ void __launch_bounds__(256) g_kernel(
    const float* __restrict__ q2, const float* __restrict__ Wpkv, float* __restrict__ g)
{
    __shared__ float As[64 * 65];
    __shared__ float Bs[64 * 65];
    const int t = threadIdx.x;
    const int m0 = blockIdx.x * 64;
    const int n0 = blockIdx.y * 64;
    const int h = blockIdx.z;

#pragma unroll
    for (int r = 0; r < 4; r++) {
        int idx = t + r * 256;
        int mm = idx >> 4;
        int dv = (idx & 15) * 4;
        float4 a = *(const float4*)(q2 + (size_t)(m0 + mm) * CC + h * 64 + dv);
        As[mm * 65 + dv + 0] = a.x;
        As[mm * 65 + dv + 1] = a.y;
        As[mm * 65 + dv + 2] = a.z;
        As[mm * 65 + dv + 3] = a.w;
        float4 bv = *(const float4*)(Wpkv + (size_t)(n0 + mm) * (2 * CC) + h * 64 + dv);
        Bs[mm * 65 + dv + 0] = bv.x;
        Bs[mm * 65 + dv + 1] = bv.y;
        Bs[mm * 65 + dv + 2] = bv.z;
        Bs[mm * 65 + dv + 3] = bv.w;
    }
    __syncthreads();

    const int tx = t & 15, ty = t >> 4;
    float acc[4][4];
#pragma unroll
    for (int i = 0; i < 4; i++)
#pragma unroll
        for (int j = 0; j < 4; j++) acc[i][j] = 0.f;
#pragma unroll 8
    for (int kk = 0; kk < 64; kk++) {
        float a[4], b[4];
#pragma unroll
        for (int i = 0; i < 4; i++) a[i] = As[(ty * 4 + i) * 65 + kk];
#pragma unroll
        for (int j = 0; j < 4; j++) b[j] = Bs[(tx * 4 + j) * 65 + kk];
#pragma unroll
        for (int i = 0; i < 4; i++)
#pragma unroll
            for (int j = 0; j < 4; j++) acc[i][j] += a[i] * b[j];
    }
#pragma unroll
    for (int i = 0; i < 4; i++) {
        float4 v = make_float4(acc[i][0], acc[i][1], acc[i][2], acc[i][3]);
        *(float4*)(g + ((size_t)(m0 + ty * 4 + i) * HH + h) * CC + n0 + tx * 4) = v;
    }
}

// ---------------- phase-2: logits + softmax + output + attn write ----------------
#define P2_SMEM_FLOATS (FF * CC + HH * CC + 96 + 96)
__global__ void __launch_bounds__(256) phase2_kernel(
    const float* __restrict__ traj, const float* __restrict__ g,
    float* __restrict__ pre, float* __restrict__ attn_out, int write_attn)
{
    extern __shared__ float sm[];
    float* trs = sm;
    float* gs = sm + FF * CC;
    float* lsm = gs + HH * CC;
    float* am = lsm + 96;

    const int bs = blockIdx.x;
    const int b = bs / SS, s = bs % SS;
    const int t = threadIdx.x;

    const float* tr = traj + (size_t)bs * FF * CC;
    for (int i = t; i < FF * CC / 4; i += 256)
        ((float4*)trs)[i] = ((const float4*)tr)[i];
    const float* gg = g + (size_t)bs * HH * CC;
    for (int i = t; i < HH * CC / 4; i += 256)
        ((float4*)gs)[i] = ((const float4*)gg)[i];
    __syncthreads();

    {
        const int lane = t & 31, w = t >> 5;
        for (int p = w * 12; p < w * 12 + 12; p++) {
            int h = p >> 3, f = p & 7;
            float ssum = 0.f;
            for (int c = lane; c < CC; c += 32)
                ssum += trs[f * CC + c] * gs[h * CC + c];
#pragma unroll
            for (int o = 16; o; o >>= 1) ssum += __shfl_xor_sync(0xffffffffu, ssum, o);
            if (lane == 0) lsm[p] = ssum;
        }
    }
    __syncthreads();

    if (t < HH) {
        int h = t;
        float m = -1e30f;
#pragma unroll
        for (int f = 0; f < FF; f++) m = fmaxf(m, lsm[h * 8 + f]);
        float e[FF];
        float ssum = 0.f;
#pragma unroll
        for (int f = 0; f < FF; f++) { e[f] = __expf(lsm[h * 8 + f] - m); ssum += e[f]; }
        float inv = 1.f / ssum;
#pragma unroll
        for (int f = 0; f < FF; f++) am[h * 8 + f] = e[f] * inv;
    }
    __syncthreads();

    if (write_attn && t < 96) {
        int h = t >> 3, f = t & 7;
        attn_out[(((size_t)b * HH + h) * SS + s) * FF + f] = am[t];
    }

    for (int c = t; c < CC; c += 256) {
        int h = c >> 6;
        float acc = 0.f;
#pragma unroll
        for (int f = 0; f < FF; f++) acc += am[h * 8 + f] * trs[f * CC + c];
        pre[((size_t)b * NTOK + 1 + s) * CC + c] = acc;
    }
}

// ---------------- host ----------------
extern "C" void kernel_launch(void* const* d_in, const int* in_sizes, int n_in,
                              void* d_out, int out_size)
{
    const float* x     = (const float*)d_in[0];
    const float* Wqkv  = (const float*)d_in[1];
    const float* Wpq   = (const float*)d_in[2];
    const float* Wpkv  = (const float*)d_in[3];
    const float* Wproj = (const float*)d_in[4];
    const float* bproj = (const float*)d_in[5];

    float *qkv, *traj, *xd, *q2, *gb, *pre;
    cudaGetSymbolAddress((void**)&qkv,  g_qkv);
    cudaGetSymbolAddress((void**)&traj, g_traj);
    cudaGetSymbolAddress((void**)&xd,   g_xd);
    cudaGetSymbolAddress((void**)&q2,   g_q2v);
    cudaGetSymbolAddress((void**)&gb,   g_gb);
    cudaGetSymbolAddress((void**)&pre,  g_pre);

    const size_t OUT_MAIN = (size_t)BB * NTOK * CC;
    const size_t OUT_ATTN = (size_t)BB * HH * SS * FF;
    int write_attn = ((size_t)out_size >= OUT_MAIN + OUT_ATTN) ? 1 : 0;
    float* attn_ptr = (float*)d_out + OUT_MAIN;

    const int spa_smem = SPA2_SMEM_FLOATS * 4;
    const int p2_smem = P2_SMEM_FLOATS * 4;
    cudaFuncSetAttribute(spatial_tc_kernel, cudaFuncAttributeMaxDynamicSharedMemorySize, spa_smem);
    cudaFuncSetAttribute(phase2_kernel,     cudaFuncAttributeMaxDynamicSharedMemorySize, p2_smem);

    // 1) qkv = x @ W_qkv  [tf32 TC]
    sgemm_tf32_kernel<<<dim3((3 * CC) / 128, (BB * NTOK + 127) / 128), 256>>>(
        x, Wqkv, qkv, BB * NTOK, 3 * CC, CC, 1.0f, nullptr);

    // 2) CLS attention -> pre[b, 0, :]
    cls_kernel<<<BB * HH, 256>>>(qkv, pre);

    // 3) spatial attention (tf32 TC, f-loop inside) -> traj
    spatial_tc_kernel<<<dim3(SS / QT, BB * HH), 128, spa_smem>>>(qkv, traj);

    // 4) x_diag gather
    {
        int tot = BB * SS * (CC / 4);
        xdiag_kernel<<<(tot + 255) / 256, 256>>>(traj, xd);
    }

    // 5) q2 = scale * x_diag @ W_pq  [tf32 TC]
    sgemm_tf32_kernel<<<dim3(CC / 128, (BB * SS + 127) / 128), 256>>>(
        xd, Wpq, q2, BB * SS, CC, CC, SCALE, nullptr);

    // 6) g = per-head W_pk @ q2
    g_kernel<<<dim3((BB * SS) / 64, CC / 64, HH), 256>>>(q2, Wpkv, gb);

    // 7) phase-2 attention
    phase2_kernel<<<BB * SS, 256, p2_smem>>>(traj, gb, pre, attn_ptr, write_attn);

    // 8) out = pre @ W_proj + b_proj  [tf32 TC]
    sgemm_tf32_kernel<<<dim3(CC / 128, (BB * NTOK + 127) / 128), 256>>>(
        pre, Wproj, (float*)d_out, BB * NTOK, CC, CC, 1.0f, bproj);
}

// round 12
// speedup vs baseline: 1.6739x; 1.0542x over previous
#include <cuda_runtime.h>
#include <cstdint>
#include <cstddef>

#define BB 2
#define NTOK 1569
#define CC 768
#define HH 12
#define PP 196
#define FF 8
#define SS 1568
#define SCALE 0.125f

// ---------------- scratch (static device globals: no allocation) ----------------
__device__ float g_qkv[(size_t)BB * NTOK * 3 * CC];   // (B*N, 2304)
__device__ float g_traj[(size_t)BB * SS * FF * CC];   // (B,S,F,C)
__device__ float g_xd[(size_t)BB * SS * CC];          // x_diag (B,S,C)
__device__ float g_q2v[(size_t)BB * SS * CC];         // q2 (B,S,C), pre-scaled
__device__ float g_gb[(size_t)BB * SS * HH * CC];     // g (B,S,H,C)
__device__ float g_pre[(size_t)BB * NTOK * CC];       // concat(cls_out, out)

// =================== tf32 helpers ===================
__device__ __forceinline__ uint32_t f2tf32(float x) {
    uint32_t r;
    asm("cvt.rna.tf32.f32 %0, %1;" : "=r"(r) : "f"(x));
    return r;
}

__device__ __forceinline__ void mma_tf32(float* d, const uint32_t* a, const uint32_t* b) {
    asm volatile(
        "mma.sync.aligned.m16n8k8.row.col.f32.tf32.tf32.f32 "
        "{%0,%1,%2,%3}, {%4,%5,%6,%7}, {%8,%9}, {%0,%1,%2,%3};"
        : "+f"(d[0]), "+f"(d[1]), "+f"(d[2]), "+f"(d[3])
        : "r"(a[0]), "r"(a[1]), "r"(a[2]), "r"(a[3]), "r"(b[0]), "r"(b[1]));
}

#define CP_ASYNC16(dst, src, srcsz) \
    asm volatile("cp.async.cg.shared.global [%0], [%1], 16, %2;" \
                 :: "r"(dst), "l"(src), "r"(srcsz))
#define CP_COMMIT() asm volatile("cp.async.commit_group;")
#define CP_WAIT0() asm volatile("cp.async.wait_group 0;")
#define CP_WAIT1() asm volatile("cp.async.wait_group 1;")

// =================== pipelined tf32 tensor-core SGEMM ===================
// C = alpha * A(MxK)@B(KxN) (+bias).  N%128==0, K%32==0, M edge guarded.
// 128x128x32 tile, 2-stage cp.async double buffer, raw-fp32 bits into mma (tf32 trunc).
#define ASTR 36   // A smem row stride (floats)
#define BSTR 136  // B smem row stride (floats)
#define A_TILE (128 * ASTR)
#define B_TILE (32 * BSTR)
#define SG_SMEM_FLOATS (2 * A_TILE + 2 * B_TILE)

__global__ void __launch_bounds__(256, 2) sgemm_tf32_kernel(
    const float* __restrict__ A, const float* __restrict__ B, float* __restrict__ C,
    int M, int N, int K, float alpha, const float* __restrict__ bias)
{
    extern __shared__ float sm[];
    float* As = sm;                    // [2][128][ASTR]
    float* Bs = sm + 2 * A_TILE;       // [2][32][BSTR]
    const uint32_t sA0 = (uint32_t)__cvta_generic_to_shared(As);
    const uint32_t sB0 = (uint32_t)__cvta_generic_to_shared(Bs);

    const int tid = threadIdx.x;
    const int lane = tid & 31;
    const int warp = tid >> 5;
    const int gid = lane >> 2;
    const int tig = lane & 3;
    const int warp_m = warp >> 1;
    const int warp_n = warp & 1;
    const int row0 = blockIdx.y * 128;
    const int col0 = blockIdx.x * 128;

    // copy task coordinates (fixed per thread)
    const int a_row[4] = { (tid + 0) >> 3, (tid + 256) >> 3, (tid + 512) >> 3, (tid + 768) >> 3 };
    const int a_kq = (tid & 7) << 2;
    const int b_k[4]  = { (tid + 0) >> 5, (tid + 256) >> 5, (tid + 512) >> 5, (tid + 768) >> 5 };
    const int b_nq = (tid & 31) << 2;

    float acc[2][8][4];
#pragma unroll
    for (int mf = 0; mf < 2; mf++)
#pragma unroll
        for (int nf = 0; nf < 8; nf++)
#pragma unroll
            for (int c = 0; c < 4; c++) acc[mf][nf][c] = 0.f;

    const int nkt = K >> 5;

    // prefetch tile 0 into buffer 0
    {
        const int k0 = 0;
#pragma unroll
        for (int r = 0; r < 4; r++) {
            int grow = row0 + a_row[r];
            const float* src = A + (size_t)grow * K + k0 + a_kq;
            uint32_t dst = sA0 + (uint32_t)((a_row[r] * ASTR + a_kq) << 2);
            CP_ASYNC16(dst, src, grow < M ? 16 : 0);
        }
#pragma unroll
        for (int r = 0; r < 4; r++) {
            const float* src = B + (size_t)(k0 + b_k[r]) * N + col0 + b_nq;
            uint32_t dst = sB0 + (uint32_t)((b_k[r] * BSTR + b_nq) << 2);
            CP_ASYNC16(dst, src, 16);
        }
        CP_COMMIT();
    }

    for (int kt = 0; kt < nkt; kt++) {
        const int cur = kt & 1;
        if (kt + 1 < nkt) {
            const int k0 = (kt + 1) << 5;
            const int nxt = cur ^ 1;
            const uint32_t aoff = sA0 + (uint32_t)(nxt * A_TILE << 2);
            const uint32_t boff = sB0 + (uint32_t)(nxt * B_TILE << 2);
#pragma unroll
            for (int r = 0; r < 4; r++) {
                int grow = row0 + a_row[r];
                const float* src = A + (size_t)grow * K + k0 + a_kq;
                uint32_t dst = aoff + (uint32_t)((a_row[r] * ASTR + a_kq) << 2);
                CP_ASYNC16(dst, src, grow < M ? 16 : 0);
            }
#pragma unroll
            for (int r = 0; r < 4; r++) {
                const float* src = B + (size_t)(k0 + b_k[r]) * N + col0 + b_nq;
                uint32_t dst = boff + (uint32_t)((b_k[r] * BSTR + b_nq) << 2);
                CP_ASYNC16(dst, src, 16);
            }
            CP_COMMIT();
            CP_WAIT1();
        } else {
            CP_WAIT0();
        }
        __syncthreads();

        const uint32_t* Acur = (const uint32_t*)(As + cur * A_TILE);
        const uint32_t* Bcur = (const uint32_t*)(Bs + cur * B_TILE);
#pragma unroll
        for (int s = 0; s < 4; s++) {
            uint32_t a[2][4];
#pragma unroll
            for (int mf = 0; mf < 2; mf++) {
                int mb = warp_m * 32 + mf * 16;
                const uint32_t* ap = Acur + (mb + gid) * ASTR + s * 8 + tig;
                a[mf][0] = ap[0];
                a[mf][1] = ap[8 * ASTR];
                a[mf][2] = ap[4];
                a[mf][3] = ap[8 * ASTR + 4];
            }
            uint32_t b[8][2];
#pragma unroll
            for (int nf = 0; nf < 8; nf++) {
                int nb = warp_n * 64 + nf * 8 + gid;
                b[nf][0] = Bcur[(s * 8 + tig) * BSTR + nb];
                b[nf][1] = Bcur[(s * 8 + tig + 4) * BSTR + nb];
            }
#pragma unroll
            for (int mf = 0; mf < 2; mf++)
#pragma unroll
                for (int nf = 0; nf < 8; nf++)
                    mma_tf32(acc[mf][nf], a[mf], b[nf]);
        }
        __syncthreads();
    }

#pragma unroll
    for (int mf = 0; mf < 2; mf++) {
        int rbase = row0 + warp_m * 32 + mf * 16 + gid;
#pragma unroll
        for (int half = 0; half < 2; half++) {
            int r = rbase + half * 8;
            if (r >= M) continue;
#pragma unroll
            for (int nf = 0; nf < 8; nf++) {
                int cidx = col0 + warp_n * 64 + nf * 8 + tig * 2;
                float2 v;
                v.x = acc[mf][nf][half * 2 + 0] * alpha;
                v.y = acc[mf][nf][half * 2 + 1] * alpha;
                if (bias) { v.x += bias[cidx]; v.y += bias[cidx + 1]; }
                *(float2*)(C + (size_t)r * N + cidx) = v;
            }
        }
    }
}

// ---------------- CLS attention: one block per (b,h) ----------------
__global__ void __launch_bounds__(256) cls_kernel(const float* __restrict__ qkv,
                                                  float* __restrict__ pre)
{
    __shared__ float qv[64];
    __shared__ float logit[NTOK];
    __shared__ float red[256];
    const int bh = blockIdx.x;
    const int b = bh / HH, h = bh % HH;
    const int t = threadIdx.x;
    const float* base = qkv + (size_t)b * NTOK * (3 * CC);

    if (t < 64) qv[t] = base[h * 64 + t] * SCALE;
    __syncthreads();

    for (int n = t; n < NTOK; n += 256) {
        const float* kr = base + (size_t)n * (3 * CC) + CC + h * 64;
        float s = 0.f;
#pragma unroll 16
        for (int dd = 0; dd < 64; dd++) s += qv[dd] * kr[dd];
        logit[n] = s;
    }
    __syncthreads();

    float m = -1e30f;
    for (int n = t; n < NTOK; n += 256) m = fmaxf(m, logit[n]);
    red[t] = m; __syncthreads();
    for (int s2 = 128; s2 > 0; s2 >>= 1) {
        if (t < s2) red[t] = fmaxf(red[t], red[t + s2]);
        __syncthreads();
    }
    const float mx = red[0];
    __syncthreads();

    float ssum = 0.f;
    for (int n = t; n < NTOK; n += 256) {
        float e = __expf(logit[n] - mx);
        logit[n] = e;
        ssum += e;
    }
    red[t] = ssum; __syncthreads();
    for (int s2 = 128; s2 > 0; s2 >>= 1) {
        if (t < s2) red[t] += red[t + s2];
        __syncthreads();
    }
    const float inv = 1.f / red[0];
    __syncthreads();

    const int dd = t & 63, grp = t >> 6;
    float acc = 0.f;
    for (int n = grp; n < NTOK; n += 4)
        acc += logit[n] * base[(size_t)n * (3 * CC) + 2 * CC + h * 64 + dd];
    red[t] = acc; __syncthreads();
    if (t < 64) {
        float v = red[t] + red[t + 64] + red[t + 128] + red[t + 192];
        pre[(size_t)b * NTOK * CC + h * 64 + t] = v * inv;
    }
}

// ---------------- tf32 tensor-core spatial attention (+ fused x_diag) ----------------
#define QT 32
#define NPAD 208
#define QSTR 68
#define KSTR 216
#define LSTR 212
#define VSTR 72
#define SPA2_POOL 14976
#define SPA2_SMEM_FLOATS (QT*QSTR + QT*LSTR + SPA2_POOL)

__global__ void __launch_bounds__(128, 2) spatial_tc_kernel(const float* __restrict__ qkv,
                                                            float* __restrict__ traj,
                                                            float* __restrict__ xd)
{
    extern __shared__ float sm[];
    uint32_t* qs = (uint32_t*)sm;               // [QT][QSTR]
    float* ls = sm + QT * QSTR;                 // [QT][LSTR]
    uint32_t* ks = (uint32_t*)(ls + QT * LSTR); // [64][KSTR]
    uint32_t* vs = ks;                          // [NPAD][VSTR] (reused)

    const int t = threadIdx.x;
    const int lane = t & 31, warp = t >> 5;
    const int gid = lane >> 2, tig = lane & 3;
    const int warp_m = warp >> 1;
    const int warp_n = warp & 1;
    const int bh = blockIdx.y;
    const int b = bh / HH, h = bh % HH;
    const int q0 = blockIdx.x * QT;
    const float* base = qkv + (size_t)b * NTOK * (3 * CC);

#pragma unroll
    for (int r = 0; r < 4; r++) {
        int idx = t + r * 128;
        int q = idx >> 4, dv = (idx & 15) << 2;
        float4 v = *(const float4*)(base + (size_t)(1 + q0 + q) * (3 * CC) + h * 64 + dv);
        uint32_t* dst = qs + q * QSTR + dv;
        dst[0] = f2tf32(v.x * SCALE); dst[1] = f2tf32(v.y * SCALE);
        dst[2] = f2tf32(v.z * SCALE); dst[3] = f2tf32(v.w * SCALE);
    }

    for (int f = 0; f < FF; f++) {
        for (int idx = t; idx < PP * 16; idx += 128) {
            int n = idx >> 4, dv = (idx & 15) << 2;
            float4 v = *(const float4*)(base + (size_t)(1 + f * PP + n) * (3 * CC) + CC + h * 64 + dv);
            ks[(dv + 0) * KSTR + n] = f2tf32(v.x);
            ks[(dv + 1) * KSTR + n] = f2tf32(v.y);
            ks[(dv + 2) * KSTR + n] = f2tf32(v.z);
            ks[(dv + 3) * KSTR + n] = f2tf32(v.w);
        }
        for (int i = t; i < 64 * 12; i += 128) {
            int d = i / 12, n = 196 + (i % 12);
            ks[d * KSTR + n] = 0u;
        }
        __syncthreads();

        // ---- QK mma ----
        {
            float acc[13][4];
#pragma unroll
            for (int nf = 0; nf < 13; nf++)
#pragma unroll
                for (int c = 0; c < 4; c++) acc[nf][c] = 0.f;
#pragma unroll
            for (int s = 0; s < 8; s++) {
                uint32_t a[4];
                const uint32_t* ap = qs + (warp_m * 16 + gid) * QSTR + s * 8 + tig;
                a[0] = ap[0];
                a[1] = ap[8 * QSTR];
                a[2] = ap[4];
                a[3] = ap[8 * QSTR + 4];
#pragma unroll
                for (int nf = 0; nf < 13; nf++) {
                    int nb = warp_n * 104 + nf * 8 + gid;
                    uint32_t bfr[2];
                    bfr[0] = ks[(s * 8 + tig) * KSTR + nb];
                    bfr[1] = ks[(s * 8 + tig + 4) * KSTR + nb];
                    mma_tf32(acc[nf], a, bfr);
                }
            }
#pragma unroll
            for (int nf = 0; nf < 13; nf++) {
                int col = warp_n * 104 + nf * 8 + tig * 2;
                int row = warp_m * 16 + gid;
                *(float2*)(ls + row * LSTR + col) = make_float2(acc[nf][0], acc[nf][1]);
                *(float2*)(ls + (row + 8) * LSTR + col) = make_float2(acc[nf][2], acc[nf][3]);
            }
        }
        __syncthreads();

        // ---- V load (overwrites K pool) ----
        for (int idx = t; idx < PP * 16; idx += 128) {
            int n = idx >> 4, dv = (idx & 15) << 2;
            float4 v = *(const float4*)(base + (size_t)(1 + f * PP + n) * (3 * CC) + 2 * CC + h * 64 + dv);
            uint32_t* dst = vs + n * VSTR + dv;
            dst[0] = f2tf32(v.x); dst[1] = f2tf32(v.y);
            dst[2] = f2tf32(v.z); dst[3] = f2tf32(v.w);
        }

        // ---- softmax (8 rows per warp), probs -> tf32, pads zeroed ----
        for (int i = 0; i < 8; i++) {
            int qq = warp * 8 + i;
            float* row = ls + qq * LSTR;
            float m = -1e30f;
            for (int n = lane; n < PP; n += 32) m = fmaxf(m, row[n]);
#pragma unroll
            for (int o = 16; o; o >>= 1) m = fmaxf(m, __shfl_xor_sync(0xffffffffu, m, o));
            float ssum = 0.f;
            float ev[7];
            int cnt = 0;
            for (int n = lane; n < PP; n += 32) {
                float e = __expf(row[n] - m);
                ev[cnt++] = e;
                ssum += e;
            }
#pragma unroll
            for (int o = 16; o; o >>= 1) ssum += __shfl_xor_sync(0xffffffffu, ssum, o);
            float inv = 1.f / ssum;
            cnt = 0;
            for (int n = lane; n < PP; n += 32)
                ((uint32_t*)row)[n] = f2tf32(ev[cnt++] * inv);
            if (lane < 12) ((uint32_t*)row)[196 + lane] = 0u;
        }
        __syncthreads();

        // ---- PV mma + epilogue (traj, fused x_diag) ----
        {
            float acc[4][4];
#pragma unroll
            for (int nf = 0; nf < 4; nf++)
#pragma unroll
                for (int c = 0; c < 4; c++) acc[nf][c] = 0.f;
            const uint32_t* lsu = (const uint32_t*)ls;
#pragma unroll
            for (int s = 0; s < 26; s++) {
                uint32_t a[4];
                const uint32_t* ap = lsu + (warp_m * 16 + gid) * LSTR + s * 8 + tig;
                a[0] = ap[0];
                a[1] = ap[8 * LSTR];
                a[2] = ap[4];
                a[3] = ap[8 * LSTR + 4];
#pragma unroll
                for (int nf = 0; nf < 4; nf++) {
                    int nb = warp_n * 32 + nf * 8 + gid;
                    uint32_t bfr[2];
                    bfr[0] = vs[(s * 8 + tig) * VSTR + nb];
                    bfr[1] = vs[(s * 8 + tig + 4) * VSTR + nb];
                    mma_tf32(acc[nf], a, bfr);
                }
            }
#pragma unroll
            for (int half = 0; half < 2; half++) {
                int q = q0 + warp_m * 16 + gid + half * 8;
                float* orow = traj + (((size_t)(b * SS + q) * FF + f) * CC + h * 64);
                const bool diag = (f == q / PP);
                float* xrow = xd + ((size_t)(b * SS + q) * CC + h * 64);
#pragma unroll
                for (int nf = 0; nf < 4; nf++) {
                    int col = warp_n * 32 + nf * 8 + tig * 2;
                    float2 v = make_float2(acc[nf][half * 2 + 0], acc[nf][half * 2 + 1]);
                    *(float2*)(orow + col) = v;
                    if (diag) *(float2*)(xrow + col) = v;
                }
            }
        }
        __syncthreads();
    }
}

// ---------------- g[b,s,h,c] = sum_d q2[bs, h*64+d] * W_pkv[c, h*64+d] ----------------
__global__ void __launch_bounds__(256) g_kernel(
    const float* __restrict__ q2, const float* __restrict__ Wpkv, float* __restrict__ g)
{
    __shared__ float As[64 * 65];
    __shared__ float Bs[64 * 65];
    const int t = threadIdx.x;
    const int m0 = blockIdx.x * 64;
    const int n0 = blockIdx.y * 64;
    const int h = blockIdx.z;

#pragma unroll
    for (int r = 0; r < 4; r++) {
        int idx = t + r * 256;
        int mm = idx >> 4;
        int dv = (idx & 15) * 4;
        float4 a = *(const float4*)(q2 + (size_t)(m0 + mm) * CC + h * 64 + dv);
        As[mm * 65 + dv + 0] = a.x;
        As[mm * 65 + dv + 1] = a.y;
        As[mm * 65 + dv + 2] = a.z;
        As[mm * 65 + dv + 3] = a.w;
        float4 bv = *(const float4*)(Wpkv + (size_t)(n0 + mm) * (2 * CC) + h * 64 + dv);
        Bs[mm * 65 + dv + 0] = bv.x;
        Bs[mm * 65 + dv + 1] = bv.y;
        Bs[mm * 65 + dv + 2] = bv.z;
        Bs[mm * 65 + dv + 3] = bv.w;
    }
    __syncthreads();

    const int tx = t & 15, ty = t >> 4;
    float acc[4][4];
#pragma unroll
    for (int i = 0; i < 4; i++)
#pragma unroll
        for (int j = 0; j < 4; j++) acc[i][j] = 0.f;
#pragma unroll 8
    for (int kk = 0; kk < 64; kk++) {
        float a[4], b[4];
#pragma unroll
        for (int i = 0; i < 4; i++) a[i] = As[(ty * 4 + i) * 65 + kk];
#pragma unroll
        for (int j = 0; j < 4; j++) b[j] = Bs[(tx * 4 + j) * 65 + kk];
#pragma unroll
        for (int i = 0; i < 4; i++)
#pragma unroll
            for (int j = 0; j < 4; j++) acc[i][j] += a[i] * b[j];
    }
#pragma unroll
    for (int i = 0; i < 4; i++) {
        float4 v = make_float4(acc[i][0], acc[i][1], acc[i][2], acc[i][3]);
        *(float4*)(g + ((size_t)(m0 + ty * 4 + i) * HH + h) * CC + n0 + tx * 4) = v;
    }
}

// ---------------- phase-2: logits + softmax + output + attn write ----------------
#define P2_SMEM_FLOATS (FF * CC + HH * CC + 96 + 96)
__global__ void __launch_bounds__(256) phase2_kernel(
    const float* __restrict__ traj, const float* __restrict__ g,
    float* __restrict__ pre, float* __restrict__ attn_out, int write_attn)
{
    extern __shared__ float sm[];
    float* trs = sm;
    float* gs = sm + FF * CC;
    float* lsm = gs + HH * CC;
    float* am = lsm + 96;

    const int bs = blockIdx.x;
    const int b = bs / SS, s = bs % SS;
    const int t = threadIdx.x;

    const float* tr = traj + (size_t)bs * FF * CC;
    for (int i = t; i < FF * CC / 4; i += 256)
        ((float4*)trs)[i] = ((const float4*)tr)[i];
    const float* gg = g + (size_t)bs * HH * CC;
    for (int i = t; i < HH * CC / 4; i += 256)
        ((float4*)gs)[i] = ((const float4*)gg)[i];
    __syncthreads();

    {
        const int lane = t & 31, w = t >> 5;
        for (int p = w * 12; p < w * 12 + 12; p++) {
            int h = p >> 3, f = p & 7;
            float ssum = 0.f;
            for (int c = lane; c < CC; c += 32)
                ssum += trs[f * CC + c] * gs[h * CC + c];
#pragma unroll
            for (int o = 16; o; o >>= 1) ssum += __shfl_xor_sync(0xffffffffu, ssum, o);
            if (lane == 0) lsm[p] = ssum;
        }
    }
    __syncthreads();

    if (t < HH) {
        int h = t;
        float m = -1e30f;
#pragma unroll
        for (int f = 0; f < FF; f++) m = fmaxf(m, lsm[h * 8 + f]);
        float e[FF];
        float ssum = 0.f;
#pragma unroll
        for (int f = 0; f < FF; f++) { e[f] = __expf(lsm[h * 8 + f] - m); ssum += e[f]; }
        float inv = 1.f / ssum;
#pragma unroll
        for (int f = 0; f < FF; f++) am[h * 8 + f] = e[f] * inv;
    }
    __syncthreads();

    if (write_attn && t < 96) {
        int h = t >> 3, f = t & 7;
        attn_out[(((size_t)b * HH + h) * SS + s) * FF + f] = am[t];
    }

    for (int c = t; c < CC; c += 256) {
        int h = c >> 6;
        float acc = 0.f;
#pragma unroll
        for (int f = 0; f < FF; f++) acc += am[h * 8 + f] * trs[f * CC + c];
        pre[((size_t)b * NTOK + 1 + s) * CC + c] = acc;
    }
}

// ---------------- host ----------------
extern "C" void kernel_launch(void* const* d_in, const int* in_sizes, int n_in,
                              void* d_out, int out_size)
{
    const float* x     = (const float*)d_in[0];
    const float* Wqkv  = (const float*)d_in[1];
    const float* Wpq   = (const float*)d_in[2];
    const float* Wpkv  = (const float*)d_in[3];
    const float* Wproj = (const float*)d_in[4];
    const float* bproj = (const float*)d_in[5];

    float *qkv, *traj, *xd, *q2, *gb, *pre;
    cudaGetSymbolAddress((void**)&qkv,  g_qkv);
    cudaGetSymbolAddress((void**)&traj, g_traj);
    cudaGetSymbolAddress((void**)&xd,   g_xd);
    cudaGetSymbolAddress((void**)&q2,   g_q2v);
    cudaGetSymbolAddress((void**)&gb,   g_gb);
    cudaGetSymbolAddress((void**)&pre,  g_pre);

    const size_t OUT_MAIN = (size_t)BB * NTOK * CC;
    const size_t OUT_ATTN = (size_t)BB * HH * SS * FF;
    int write_attn = ((size_t)out_size >= OUT_MAIN + OUT_ATTN) ? 1 : 0;
    float* attn_ptr = (float*)d_out + OUT_MAIN;

    const int sg_smem  = SG_SMEM_FLOATS * 4;
    const int spa_smem = SPA2_SMEM_FLOATS * 4;
    const int p2_smem  = P2_SMEM_FLOATS * 4;
    cudaFuncSetAttribute(sgemm_tf32_kernel, cudaFuncAttributeMaxDynamicSharedMemorySize, sg_smem);
    cudaFuncSetAttribute(spatial_tc_kernel, cudaFuncAttributeMaxDynamicSharedMemorySize, spa_smem);
    cudaFuncSetAttribute(phase2_kernel,     cudaFuncAttributeMaxDynamicSharedMemorySize, p2_smem);

    // 1) qkv = x @ W_qkv  [tf32 TC, pipelined]
    sgemm_tf32_kernel<<<dim3((3 * CC) / 128, (BB * NTOK + 127) / 128), 256, sg_smem>>>(
        x, Wqkv, qkv, BB * NTOK, 3 * CC, CC, 1.0f, nullptr);

    // 2) CLS attention -> pre[b, 0, :]
    cls_kernel<<<BB * HH, 256>>>(qkv, pre);

    // 3) spatial attention (tf32 TC) -> traj, with fused x_diag -> xd
    spatial_tc_kernel<<<dim3(SS / QT, BB * HH), 128, spa_smem>>>(qkv, traj, xd);

    // 4) q2 = scale * x_diag @ W_pq  [tf32 TC, pipelined]
    sgemm_tf32_kernel<<<dim3(CC / 128, (BB * SS + 127) / 128), 256, sg_smem>>>(
        xd, Wpq, q2, BB * SS, CC, CC, SCALE, nullptr);

    // 5) g = per-head W_pk @ q2
    g_kernel<<<dim3((BB * SS) / 64, CC / 64, HH), 256>>>(q2, Wpkv, gb);

    // 6) phase-2 attention
    phase2_kernel<<<BB * SS, 256, p2_smem>>>(traj, gb, pre, attn_ptr, write_attn);

    // 7) out = pre @ W_proj + b_proj  [tf32 TC, pipelined]
    sgemm_tf32_kernel<<<dim3(CC / 128, (BB * NTOK + 127) / 128), 256, sg_smem>>>(
        pre, Wproj, (float*)d_out, BB * NTOK, CC, CC, 1.0f, bproj);
}

// round 13
// speedup vs baseline: 1.8224x; 1.0887x over previous
#include <cuda_runtime.h>
#include <cstdint>
#include <cstddef>

#define BB 2
#define NTOK 1569
#define CC 768
#define HH 12
#define PP 196
#define FF 8
#define SS 1568
#define SCALE 0.125f

// ---------------- scratch (static device globals: no allocation) ----------------
__device__ float g_qkv[(size_t)BB * NTOK * 3 * CC];   // (B*N, 2304)
__device__ float g_traj[(size_t)BB * SS * FF * CC];   // (B,S,F,C)
__device__ float g_xd[(size_t)BB * SS * CC];          // x_diag (B,S,C)
__device__ float g_q2v[(size_t)BB * SS * CC];         // q2 (B,S,C), pre-scaled
__device__ float g_gb[(size_t)BB * SS * HH * CC];     // g (B,S,H,C)
__device__ float g_pre[(size_t)BB * NTOK * CC];       // concat(cls_out, out)

// =================== tf32 helpers ===================
__device__ __forceinline__ uint32_t f2tf32(float x) {
    uint32_t r;
    asm("cvt.rna.tf32.f32 %0, %1;" : "=r"(r) : "f"(x));
    return r;
}

__device__ __forceinline__ void mma_tf32(float* d, const uint32_t* a, const uint32_t* b) {
    asm volatile(
        "mma.sync.aligned.m16n8k8.row.col.f32.tf32.tf32.f32 "
        "{%0,%1,%2,%3}, {%4,%5,%6,%7}, {%8,%9}, {%0,%1,%2,%3};"
        : "+f"(d[0]), "+f"(d[1]), "+f"(d[2]), "+f"(d[3])
        : "r"(a[0]), "r"(a[1]), "r"(a[2]), "r"(a[3]), "r"(b[0]), "r"(b[1]));
}

#define CP_ASYNC16(dst, src, srcsz) \
    asm volatile("cp.async.cg.shared.global [%0], [%1], 16, %2;" \
                 :: "r"(dst), "l"(src), "r"(srcsz))
#define CP_COMMIT() asm volatile("cp.async.commit_group;")
#define CP_WAIT0() asm volatile("cp.async.wait_group 0;")
#define CP_WAIT1() asm volatile("cp.async.wait_group 1;")

// =================== pipelined tf32 SGEMM, 128x128x32 tile ===================
// C = alpha * A(MxK)@B(KxN) (+bias).  N%128==0, K%32==0, M edge guarded.
// Fragments are rounded to tf32 (cvt.rna) after the smem load.
#define ASTR 36
#define BSTR 136
#define A_TILE (128 * ASTR)
#define B_TILE (32 * BSTR)
#define SG_SMEM_FLOATS (2 * A_TILE + 2 * B_TILE)

__global__ void __launch_bounds__(256, 2) sgemm_tf32_kernel(
    const float* __restrict__ A, const float* __restrict__ B, float* __restrict__ C,
    int M, int N, int K, float alpha, const float* __restrict__ bias)
{
    extern __shared__ float sm[];
    float* As = sm;
    float* Bs = sm + 2 * A_TILE;
    const uint32_t sA0 = (uint32_t)__cvta_generic_to_shared(As);
    const uint32_t sB0 = (uint32_t)__cvta_generic_to_shared(Bs);

    const int tid = threadIdx.x;
    const int lane = tid & 31;
    const int warp = tid >> 5;
    const int gid = lane >> 2;
    const int tig = lane & 3;
    const int warp_m = warp >> 1;
    const int warp_n = warp & 1;
    const int row0 = blockIdx.y * 128;
    const int col0 = blockIdx.x * 128;

    const int a_row[4] = { (tid + 0) >> 3, (tid + 256) >> 3, (tid + 512) >> 3, (tid + 768) >> 3 };
    const int a_kq = (tid & 7) << 2;
    const int b_k[4]  = { (tid + 0) >> 5, (tid + 256) >> 5, (tid + 512) >> 5, (tid + 768) >> 5 };
    const int b_nq = (tid & 31) << 2;

    float acc[2][8][4];
#pragma unroll
    for (int mf = 0; mf < 2; mf++)
#pragma unroll
        for (int nf = 0; nf < 8; nf++)
#pragma unroll
            for (int c = 0; c < 4; c++) acc[mf][nf][c] = 0.f;

    const int nkt = K >> 5;

    {
#pragma unroll
        for (int r = 0; r < 4; r++) {
            int grow = row0 + a_row[r];
            const float* src = A + (size_t)grow * K + a_kq;
            uint32_t dst = sA0 + (uint32_t)((a_row[r] * ASTR + a_kq) << 2);
            CP_ASYNC16(dst, src, grow < M ? 16 : 0);
        }
#pragma unroll
        for (int r = 0; r < 4; r++) {
            const float* src = B + (size_t)b_k[r] * N + col0 + b_nq;
            uint32_t dst = sB0 + (uint32_t)((b_k[r] * BSTR + b_nq) << 2);
            CP_ASYNC16(dst, src, 16);
        }
        CP_COMMIT();
    }

    for (int kt = 0; kt < nkt; kt++) {
        const int cur = kt & 1;
        if (kt + 1 < nkt) {
            const int k0 = (kt + 1) << 5;
            const int nxt = cur ^ 1;
            const uint32_t aoff = sA0 + (uint32_t)(nxt * A_TILE << 2);
            const uint32_t boff = sB0 + (uint32_t)(nxt * B_TILE << 2);
#pragma unroll
            for (int r = 0; r < 4; r++) {
                int grow = row0 + a_row[r];
                const float* src = A + (size_t)grow * K + k0 + a_kq;
                uint32_t dst = aoff + (uint32_t)((a_row[r] * ASTR + a_kq) << 2);
                CP_ASYNC16(dst, src, grow < M ? 16 : 0);
            }
#pragma unroll
            for (int r = 0; r < 4; r++) {
                const float* src = B + (size_t)(k0 + b_k[r]) * N + col0 + b_nq;
                uint32_t dst = boff + (uint32_t)((b_k[r] * BSTR + b_nq) << 2);
                CP_ASYNC16(dst, src, 16);
            }
            CP_COMMIT();
            CP_WAIT1();
        } else {
            CP_WAIT0();
        }
        __syncthreads();

        const float* Acur = As + cur * A_TILE;
        const float* Bcur = Bs + cur * B_TILE;
#pragma unroll
        for (int s = 0; s < 4; s++) {
            uint32_t a[2][4];
#pragma unroll
            for (int mf = 0; mf < 2; mf++) {
                int mb = warp_m * 32 + mf * 16;
                const float* ap = Acur + (mb + gid) * ASTR + s * 8 + tig;
                a[mf][0] = f2tf32(ap[0]);
                a[mf][1] = f2tf32(ap[8 * ASTR]);
                a[mf][2] = f2tf32(ap[4]);
                a[mf][3] = f2tf32(ap[8 * ASTR + 4]);
            }
            uint32_t b[8][2];
#pragma unroll
            for (int nf = 0; nf < 8; nf++) {
                int nb = warp_n * 64 + nf * 8 + gid;
                b[nf][0] = f2tf32(Bcur[(s * 8 + tig) * BSTR + nb]);
                b[nf][1] = f2tf32(Bcur[(s * 8 + tig + 4) * BSTR + nb]);
            }
#pragma unroll
            for (int mf = 0; mf < 2; mf++)
#pragma unroll
                for (int nf = 0; nf < 8; nf++)
                    mma_tf32(acc[mf][nf], a[mf], b[nf]);
        }
        __syncthreads();
    }

#pragma unroll
    for (int mf = 0; mf < 2; mf++) {
        int rbase = row0 + warp_m * 32 + mf * 16 + gid;
#pragma unroll
        for (int half = 0; half < 2; half++) {
            int r = rbase + half * 8;
            if (r >= M) continue;
#pragma unroll
            for (int nf = 0; nf < 8; nf++) {
                int cidx = col0 + warp_n * 64 + nf * 8 + tig * 2;
                float2 v;
                v.x = acc[mf][nf][half * 2 + 0] * alpha;
                v.y = acc[mf][nf][half * 2 + 1] * alpha;
                if (bias) { v.x += bias[cidx]; v.y += bias[cidx + 1]; }
                *(float2*)(C + (size_t)r * N + cidx) = v;
            }
        }
    }
}

// =================== pipelined tf32 SGEMM, 64x128x32 tile (high-occupancy) ===================
#define A_TILE64 (64 * ASTR)
#define SG64_SMEM_FLOATS (2 * A_TILE64 + 2 * B_TILE)

__global__ void __launch_bounds__(256, 3) sgemm64_tf32_kernel(
    const float* __restrict__ A, const float* __restrict__ B, float* __restrict__ C,
    int M, int N, int K, float alpha, const float* __restrict__ bias)
{
    extern __shared__ float sm[];
    float* As = sm;
    float* Bs = sm + 2 * A_TILE64;
    const uint32_t sA0 = (uint32_t)__cvta_generic_to_shared(As);
    const uint32_t sB0 = (uint32_t)__cvta_generic_to_shared(Bs);

    const int tid = threadIdx.x;
    const int lane = tid & 31;
    const int warp = tid >> 5;
    const int gid = lane >> 2;
    const int tig = lane & 3;
    const int warp_m = warp >> 1;   // 0..3 -> 16 rows each
    const int warp_n = warp & 1;    // 0..1 -> 64 cols each
    const int row0 = blockIdx.y * 64;
    const int col0 = blockIdx.x * 128;

    const int a_row[2] = { (tid + 0) >> 3, (tid + 256) >> 3 };
    const int a_kq = (tid & 7) << 2;
    const int b_k[4]  = { (tid + 0) >> 5, (tid + 256) >> 5, (tid + 512) >> 5, (tid + 768) >> 5 };
    const int b_nq = (tid & 31) << 2;

    float acc[8][4];
#pragma unroll
    for (int nf = 0; nf < 8; nf++)
#pragma unroll
        for (int c = 0; c < 4; c++) acc[nf][c] = 0.f;

    const int nkt = K >> 5;

    {
#pragma unroll
        for (int r = 0; r < 2; r++) {
            int grow = row0 + a_row[r];
            const float* src = A + (size_t)grow * K + a_kq;
            uint32_t dst = sA0 + (uint32_t)((a_row[r] * ASTR + a_kq) << 2);
            CP_ASYNC16(dst, src, grow < M ? 16 : 0);
        }
#pragma unroll
        for (int r = 0; r < 4; r++) {
            const float* src = B + (size_t)b_k[r] * N + col0 + b_nq;
            uint32_t dst = sB0 + (uint32_t)((b_k[r] * BSTR + b_nq) << 2);
            CP_ASYNC16(dst, src, 16);
        }
        CP_COMMIT();
    }

    for (int kt = 0; kt < nkt; kt++) {
        const int cur = kt & 1;
        if (kt + 1 < nkt) {
            const int k0 = (kt + 1) << 5;
            const int nxt = cur ^ 1;
            const uint32_t aoff = sA0 + (uint32_t)(nxt * A_TILE64 << 2);
            const uint32_t boff = sB0 + (uint32_t)(nxt * B_TILE << 2);
#pragma unroll
            for (int r = 0; r < 2; r++) {
                int grow = row0 + a_row[r];
                const float* src = A + (size_t)grow * K + k0 + a_kq;
                uint32_t dst = aoff + (uint32_t)((a_row[r] * ASTR + a_kq) << 2);
                CP_ASYNC16(dst, src, grow < M ? 16 : 0);
            }
#pragma unroll
            for (int r = 0; r < 4; r++) {
                const float* src = B + (size_t)(k0 + b_k[r]) * N + col0 + b_nq;
                uint32_t dst = boff + (uint32_t)((b_k[r] * BSTR + b_nq) << 2);
                CP_ASYNC16(dst, src, 16);
            }
            CP_COMMIT();
            CP_WAIT1();
        } else {
            CP_WAIT0();
        }
        __syncthreads();

        const float* Acur = As + cur * A_TILE64;
        const float* Bcur = Bs + cur * B_TILE;
#pragma unroll
        for (int s = 0; s < 4; s++) {
            uint32_t a[4];
            {
                const float* ap = Acur + (warp_m * 16 + gid) * ASTR + s * 8 + tig;
                a[0] = f2tf32(ap[0]);
                a[1] = f2tf32(ap[8 * ASTR]);
                a[2] = f2tf32(ap[4]);
                a[3] = f2tf32(ap[8 * ASTR + 4]);
            }
            uint32_t b[8][2];
#pragma unroll
            for (int nf = 0; nf < 8; nf++) {
                int nb = warp_n * 64 + nf * 8 + gid;
                b[nf][0] = f2tf32(Bcur[(s * 8 + tig) * BSTR + nb]);
                b[nf][1] = f2tf32(Bcur[(s * 8 + tig + 4) * BSTR + nb]);
            }
#pragma unroll
            for (int nf = 0; nf < 8; nf++)
                mma_tf32(acc[nf], a, b[nf]);
        }
        __syncthreads();
    }

    {
        int rbase = row0 + warp_m * 16 + gid;
#pragma unroll
        for (int half = 0; half < 2; half++) {
            int r = rbase + half * 8;
            if (r >= M) continue;
#pragma unroll
            for (int nf = 0; nf < 8; nf++) {
                int cidx = col0 + warp_n * 64 + nf * 8 + tig * 2;
                float2 v;
                v.x = acc[nf][half * 2 + 0] * alpha;
                v.y = acc[nf][half * 2 + 1] * alpha;
                if (bias) { v.x += bias[cidx]; v.y += bias[cidx + 1]; }
                *(float2*)(C + (size_t)r * N + cidx) = v;
            }
        }
    }
}

// =================== tf32 TC g-GEMM (batched per head) ===================
// g[m, h, c] = sum_d q2[m, h*64+d] * Wpkv[c, h*64+d]
// Tile 64(M) x 128(N), K=64 single shot. A [m][k] stride 68; B natural [n][k] stride 68
// (frag reads transposed: banks gid*4+tig, conflict-free). grid (49, 6, 12).
#define GSTR 68
#define G_SMEM_FLOATS (64 * GSTR + 128 * GSTR)

__global__ void __launch_bounds__(256, 3) g_tc_kernel(
    const float* __restrict__ q2, const float* __restrict__ Wpkv, float* __restrict__ g)
{
    extern __shared__ float sm[];
    float* Asm = sm;                 // [64][GSTR]
    float* Bsm = sm + 64 * GSTR;     // [128][GSTR]  (natural [n][k])

    const int t = threadIdx.x;
    const int lane = t & 31;
    const int warp = t >> 5;
    const int gid = lane >> 2;
    const int tig = lane & 3;
    const int warp_m = warp >> 1;   // 0..3
    const int warp_n = warp & 1;    // 0..1
    const int m0 = blockIdx.x * 64;
    const int n0 = blockIdx.y * 128;
    const int h = blockIdx.z;

    // A fill: 64 rows x 16 quads = 1024 tasks
#pragma unroll
    for (int r = 0; r < 4; r++) {
        int idx = t + (r << 8);
        int mm = idx >> 4, dv = (idx & 15) << 2;
        float4 v = *(const float4*)(q2 + (size_t)(m0 + mm) * CC + h * 64 + dv);
        float4 o;
        o.x = __uint_as_float(f2tf32(v.x));
        o.y = __uint_as_float(f2tf32(v.y));
        o.z = __uint_as_float(f2tf32(v.z));
        o.w = __uint_as_float(f2tf32(v.w));
        *(float4*)(Asm + mm * GSTR + dv) = o;
    }
    // B fill: 128 rows x 16 quads = 2048 tasks (natural layout, coalesced)
#pragma unroll
    for (int r = 0; r < 8; r++) {
        int idx = t + (r << 8);
        int cc = idx >> 4, dv = (idx & 15) << 2;
        float4 v = *(const float4*)(Wpkv + (size_t)(n0 + cc) * (2 * CC) + h * 64 + dv);
        float4 o;
        o.x = __uint_as_float(f2tf32(v.x));
        o.y = __uint_as_float(f2tf32(v.y));
        o.z = __uint_as_float(f2tf32(v.z));
        o.w = __uint_as_float(f2tf32(v.w));
        *(float4*)(Bsm + cc * GSTR + dv) = o;
    }
    __syncthreads();

    float acc[8][4];
#pragma unroll
    for (int nf = 0; nf < 8; nf++)
#pragma unroll
        for (int c = 0; c < 4; c++) acc[nf][c] = 0.f;

    const uint32_t* Au = (const uint32_t*)Asm;
    const uint32_t* Bu = (const uint32_t*)Bsm;
#pragma unroll
    for (int s = 0; s < 8; s++) {
        uint32_t a[4];
        const uint32_t* ap = Au + (warp_m * 16 + gid) * GSTR + s * 8 + tig;
        a[0] = ap[0];
        a[1] = ap[8 * GSTR];
        a[2] = ap[4];
        a[3] = ap[8 * GSTR + 4];
#pragma unroll
        for (int nf = 0; nf < 8; nf++) {
            int nb = warp_n * 64 + nf * 8 + gid;
            uint32_t b[2];
            b[0] = Bu[nb * GSTR + s * 8 + tig];       // B[n][k] read transposed
            b[1] = Bu[nb * GSTR + s * 8 + tig + 4];
            mma_tf32(acc[nf], a, b);
        }
    }

#pragma unroll
    for (int half = 0; half < 2; half++) {
        int m = m0 + warp_m * 16 + gid + half * 8;
        float* grow = g + ((size_t)m * HH + h) * CC + n0;
#pragma unroll
        for (int nf = 0; nf < 8; nf++) {
            int col = warp_n * 64 + nf * 8 + tig * 2;
            *(float2*)(grow + col) =
                make_float2(acc[nf][half * 2 + 0], acc[nf][half * 2 + 1]);
        }
    }
}

// ---------------- CLS attention: one block per (b,h) ----------------
__global__ void __launch_bounds__(256) cls_kernel(const float* __restrict__ qkv,
                                                  float* __restrict__ pre)
{
    __shared__ float qv[64];
    __shared__ float logit[NTOK];
    __shared__ float red[256];
    const int bh = blockIdx.x;
    const int b = bh / HH, h = bh % HH;
    const int t = threadIdx.x;
    const float* base = qkv + (size_t)b * NTOK * (3 * CC);

    if (t < 64) qv[t] = base[h * 64 + t] * SCALE;
    __syncthreads();

    for (int n = t; n < NTOK; n += 256) {
        const float* kr = base + (size_t)n * (3 * CC) + CC + h * 64;
        float s = 0.f;
#pragma unroll 16
        for (int dd = 0; dd < 64; dd++) s += qv[dd] * kr[dd];
        logit[n] = s;
    }
    __syncthreads();

    float m = -1e30f;
    for (int n = t; n < NTOK; n += 256) m = fmaxf(m, logit[n]);
    red[t] = m; __syncthreads();
    for (int s2 = 128; s2 > 0; s2 >>= 1) {
        if (t < s2) red[t] = fmaxf(red[t], red[t + s2]);
        __syncthreads();
    }
    const float mx = red[0];
    __syncthreads();

    float ssum = 0.f;
    for (int n = t; n < NTOK; n += 256) {
        float e = __expf(logit[n] - mx);
        logit[n] = e;
        ssum += e;
    }
    red[t] = ssum; __syncthreads();
    for (int s2 = 128; s2 > 0; s2 >>= 1) {
        if (t < s2) red[t] += red[t + s2];
        __syncthreads();
    }
    const float inv = 1.f / red[0];
    __syncthreads();

    const int dd = t & 63, grp = t >> 6;
    float acc = 0.f;
    for (int n = grp; n < NTOK; n += 4)
        acc += logit[n] * base[(size_t)n * (3 * CC) + 2 * CC + h * 64 + dd];
    red[t] = acc; __syncthreads();
    if (t < 64) {
        float v = red[t] + red[t + 64] + red[t + 128] + red[t + 192];
        pre[(size_t)b * NTOK * CC + h * 64 + t] = v * inv;
    }
}

// ---------------- tf32 tensor-core spatial attention (+ fused x_diag) ----------------
#define QT 32
#define NPAD 208
#define QSTR 68
#define KSTR 216
#define LSTR 212
#define VSTR 72
#define SPA2_POOL 14976
#define SPA2_SMEM_FLOATS (QT*QSTR + QT*LSTR + SPA2_POOL)

__global__ void __launch_bounds__(128, 2) spatial_tc_kernel(const float* __restrict__ qkv,
                                                            float* __restrict__ traj,
                                                            float* __restrict__ xd)
{
    extern __shared__ float sm[];
    uint32_t* qs = (uint32_t*)sm;               // [QT][QSTR]
    float* ls = sm + QT * QSTR;                 // [QT][LSTR]
    uint32_t* ks = (uint32_t*)(ls + QT * LSTR); // [64][KSTR]
    uint32_t* vs = ks;                          // [NPAD][VSTR] (reused)

    const int t = threadIdx.x;
    const int lane = t & 31, warp = t >> 5;
    const int gid = lane >> 2, tig = lane & 3;
    const int warp_m = warp >> 1;
    const int warp_n = warp & 1;
    const int bh = blockIdx.y;
    const int b = bh / HH, h = bh % HH;
    const int q0 = blockIdx.x * QT;
    const float* base = qkv + (size_t)b * NTOK * (3 * CC);

#pragma unroll
    for (int r = 0; r < 4; r++) {
        int idx = t + r * 128;
        int q = idx >> 4, dv = (idx & 15) << 2;
        float4 v = *(const float4*)(base + (size_t)(1 + q0 + q) * (3 * CC) + h * 64 + dv);
        uint32_t* dst = qs + q * QSTR + dv;
        dst[0] = f2tf32(v.x * SCALE); dst[1] = f2tf32(v.y * SCALE);
        dst[2] = f2tf32(v.z * SCALE); dst[3] = f2tf32(v.w * SCALE);
    }

    for (int f = 0; f < FF; f++) {
        for (int idx = t; idx < PP * 16; idx += 128) {
            int n = idx >> 4, dv = (idx & 15) << 2;
            float4 v = *(const float4*)(base + (size_t)(1 + f * PP + n) * (3 * CC) + CC + h * 64 + dv);
            ks[(dv + 0) * KSTR + n] = f2tf32(v.x);
            ks[(dv + 1) * KSTR + n] = f2tf32(v.y);
            ks[(dv + 2) * KSTR + n] = f2tf32(v.z);
            ks[(dv + 3) * KSTR + n] = f2tf32(v.w);
        }
        for (int i = t; i < 64 * 12; i += 128) {
            int d = i / 12, n = 196 + (i % 12);
            ks[d * KSTR + n] = 0u;
        }
        __syncthreads();

        // ---- QK mma ----
        {
            float acc[13][4];
#pragma unroll
            for (int nf = 0; nf < 13; nf++)
#pragma unroll
                for (int c = 0; c < 4; c++) acc[nf][c] = 0.f;
#pragma unroll
            for (int s = 0; s < 8; s++) {
                uint32_t a[4];
                const uint32_t* ap = qs + (warp_m * 16 + gid) * QSTR + s * 8 + tig;
                a[0] = ap[0];
                a[1] = ap[8 * QSTR];
                a[2] = ap[4];
                a[3] = ap[8 * QSTR + 4];
#pragma unroll
                for (int nf = 0; nf < 13; nf++) {
                    int nb = warp_n * 104 + nf * 8 + gid;
                    uint32_t bfr[2];
                    bfr[0] = ks[(s * 8 + tig) * KSTR + nb];
                    bfr[1] = ks[(s * 8 + tig + 4) * KSTR + nb];
                    mma_tf32(acc[nf], a, bfr);
                }
            }
#pragma unroll
            for (int nf = 0; nf < 13; nf++) {
                int col = warp_n * 104 + nf * 8 + tig * 2;
                int row = warp_m * 16 + gid;
                *(float2*)(ls + row * LSTR + col) = make_float2(acc[nf][0], acc[nf][1]);
                *(float2*)(ls + (row + 8) * LSTR + col) = make_float2(acc[nf][2], acc[nf][3]);
            }
        }
        __syncthreads();

        // ---- V load (overwrites K pool) ----
        for (int idx = t; idx < PP * 16; idx += 128) {
            int n = idx >> 4, dv = (idx & 15) << 2;
            float4 v = *(const float4*)(base + (size_t)(1 + f * PP + n) * (3 * CC) + 2 * CC + h * 64 + dv);
            uint32_t* dst = vs + n * VSTR + dv;
            dst[0] = f2tf32(v.x); dst[1] = f2tf32(v.y);
            dst[2] = f2tf32(v.z); dst[3] = f2tf32(v.w);
        }

        // ---- softmax (8 rows per warp), probs -> tf32, pads zeroed ----
        for (int i = 0; i < 8; i++) {
            int qq = warp * 8 + i;
            float* row = ls + qq * LSTR;
            float m = -1e30f;
            for (int n = lane; n < PP; n += 32) m = fmaxf(m, row[n]);
#pragma unroll
            for (int o = 16; o; o >>= 1) m = fmaxf(m, __shfl_xor_sync(0xffffffffu, m, o));
            float ssum = 0.f;
            float ev[7];
            int cnt = 0;
            for (int n = lane; n < PP; n += 32) {
                float e = __expf(row[n] - m);
                ev[cnt++] = e;
                ssum += e;
            }
#pragma unroll
            for (int o = 16; o; o >>= 1) ssum += __shfl_xor_sync(0xffffffffu, ssum, o);
            float inv = 1.f / ssum;
            cnt = 0;
            for (int n = lane; n < PP; n += 32)
                ((uint32_t*)row)[n] = f2tf32(ev[cnt++] * inv);
            if (lane < 12) ((uint32_t*)row)[196 + lane] = 0u;
        }
        __syncthreads();

        // ---- PV mma + epilogue (traj, fused x_diag) ----
        {
            float acc[4][4];
#pragma unroll
            for (int nf = 0; nf < 4; nf++)
#pragma unroll
                for (int c = 0; c < 4; c++) acc[nf][c] = 0.f;
            const uint32_t* lsu = (const uint32_t*)ls;
#pragma unroll
            for (int s = 0; s < 26; s++) {
                uint32_t a[4];
                const uint32_t* ap = lsu + (warp_m * 16 + gid) * LSTR + s * 8 + tig;
                a[0] = ap[0];
                a[1] = ap[8 * LSTR];
                a[2] = ap[4];
                a[3] = ap[8 * LSTR + 4];
#pragma unroll
                for (int nf = 0; nf < 4; nf++) {
                    int nb = warp_n * 32 + nf * 8 + gid;
                    uint32_t bfr[2];
                    bfr[0] = vs[(s * 8 + tig) * VSTR + nb];
                    bfr[1] = vs[(s * 8 + tig + 4) * VSTR + nb];
                    mma_tf32(acc[nf], a, bfr);
                }
            }
#pragma unroll
            for (int half = 0; half < 2; half++) {
                int q = q0 + warp_m * 16 + gid + half * 8;
                float* orow = traj + (((size_t)(b * SS + q) * FF + f) * CC + h * 64);
                const bool diag = (f == q / PP);
                float* xrow = xd + ((size_t)(b * SS + q) * CC + h * 64);
#pragma unroll
                for (int nf = 0; nf < 4; nf++) {
                    int col = warp_n * 32 + nf * 8 + tig * 2;
                    float2 v = make_float2(acc[nf][half * 2 + 0], acc[nf][half * 2 + 1]);
                    *(float2*)(orow + col) = v;
                    if (diag) *(float2*)(xrow + col) = v;
                }
            }
        }
        __syncthreads();
    }
}

// ---------------- phase-2: logits + softmax + output + attn write ----------------
#define P2_SMEM_FLOATS (FF * CC + HH * CC + 96 + 96)
__global__ void __launch_bounds__(256) phase2_kernel(
    const float* __restrict__ traj, const float* __restrict__ g,
    float* __restrict__ pre, float* __restrict__ attn_out, int write_attn)
{
    extern __shared__ float sm[];
    float* trs = sm;
    float* gs = sm + FF * CC;
    float* lsm = gs + HH * CC;
    float* am = lsm + 96;

    const int bs = blockIdx.x;
    const int b = bs / SS, s = bs % SS;
    const int t = threadIdx.x;

    const float* tr = traj + (size_t)bs * FF * CC;
    for (int i = t; i < FF * CC / 4; i += 256)
        ((float4*)trs)[i] = ((const float4*)tr)[i];
    const float* gg = g + (size_t)bs * HH * CC;
    for (int i = t; i < HH * CC / 4; i += 256)
        ((float4*)gs)[i] = ((const float4*)gg)[i];
    __syncthreads();

    {
        const int lane = t & 31, w = t >> 5;
        for (int p = w * 12; p < w * 12 + 12; p++) {
            int h = p >> 3, f = p & 7;
            float ssum = 0.f;
            for (int c = lane; c < CC; c += 32)
                ssum += trs[f * CC + c] * gs[h * CC + c];
#pragma unroll
            for (int o = 16; o; o >>= 1) ssum += __shfl_xor_sync(0xffffffffu, ssum, o);
            if (lane == 0) lsm[p] = ssum;
        }
    }
    __syncthreads();

    if (t < HH) {
        int h = t;
        float m = -1e30f;
#pragma unroll
        for (int f = 0; f < FF; f++) m = fmaxf(m, lsm[h * 8 + f]);
        float e[FF];
        float ssum = 0.f;
#pragma unroll
        for (int f = 0; f < FF; f++) { e[f] = __expf(lsm[h * 8 + f] - m); ssum += e[f]; }
        float inv = 1.f / ssum;
#pragma unroll
        for (int f = 0; f < FF; f++) am[h * 8 + f] = e[f] * inv;
    }
    __syncthreads();

    if (write_attn && t < 96) {
        int h = t >> 3, f = t & 7;
        attn_out[(((size_t)b * HH + h) * SS + s) * FF + f] = am[t];
    }

    for (int c = t; c < CC; c += 256) {
        int h = c >> 6;
        float acc = 0.f;
#pragma unroll
        for (int f = 0; f < FF; f++) acc += am[h * 8 + f] * trs[f * CC + c];
        pre[((size_t)b * NTOK + 1 + s) * CC + c] = acc;
    }
}

// ---------------- host ----------------
extern "C" void kernel_launch(void* const* d_in, const int* in_sizes, int n_in,
                              void* d_out, int out_size)
{
    const float* x     = (const float*)d_in[0];
    const float* Wqkv  = (const float*)d_in[1];
    const float* Wpq   = (const float*)d_in[2];
    const float* Wpkv  = (const float*)d_in[3];
    const float* Wproj = (const float*)d_in[4];
    const float* bproj = (const float*)d_in[5];

    float *qkv, *traj, *xd, *q2, *gb, *pre;
    cudaGetSymbolAddress((void**)&qkv,  g_qkv);
    cudaGetSymbolAddress((void**)&traj, g_traj);
    cudaGetSymbolAddress((void**)&xd,   g_xd);
    cudaGetSymbolAddress((void**)&q2,   g_q2v);
    cudaGetSymbolAddress((void**)&gb,   g_gb);
    cudaGetSymbolAddress((void**)&pre,  g_pre);

    const size_t OUT_MAIN = (size_t)BB * NTOK * CC;
    const size_t OUT_ATTN = (size_t)BB * HH * SS * FF;
    int write_attn = ((size_t)out_size >= OUT_MAIN + OUT_ATTN) ? 1 : 0;
    float* attn_ptr = (float*)d_out + OUT_MAIN;

    const int sg_smem   = SG_SMEM_FLOATS * 4;
    const int sg64_smem = SG64_SMEM_FLOATS * 4;
    const int g_smem    = G_SMEM_FLOATS * 4;
    const int spa_smem  = SPA2_SMEM_FLOATS * 4;
    const int p2_smem   = P2_SMEM_FLOATS * 4;
    cudaFuncSetAttribute(sgemm_tf32_kernel,   cudaFuncAttributeMaxDynamicSharedMemorySize, sg_smem);
    cudaFuncSetAttribute(sgemm64_tf32_kernel, cudaFuncAttributeMaxDynamicSharedMemorySize, sg64_smem);
    cudaFuncSetAttribute(g_tc_kernel,         cudaFuncAttributeMaxDynamicSharedMemorySize, g_smem);
    cudaFuncSetAttribute(spatial_tc_kernel,   cudaFuncAttributeMaxDynamicSharedMemorySize, spa_smem);
    cudaFuncSetAttribute(phase2_kernel,       cudaFuncAttributeMaxDynamicSharedMemorySize, p2_smem);

    // 1) qkv = x @ W_qkv  [tf32 TC, 128-tile]
    sgemm_tf32_kernel<<<dim3((3 * CC) / 128, (BB * NTOK + 127) / 128), 256, sg_smem>>>(
        x, Wqkv, qkv, BB * NTOK, 3 * CC, CC, 1.0f, nullptr);

    // 2) CLS attention -> pre[b, 0, :]
    cls_kernel<<<BB * HH, 256>>>(qkv, pre);

    // 3) spatial attention (tf32 TC) -> traj, fused x_diag -> xd
    spatial_tc_kernel<<<dim3(SS / QT, BB * HH), 128, spa_smem>>>(qkv, traj, xd);

    // 4) q2 = scale * x_diag @ W_pq  [tf32 TC, 64-tile high-occupancy]
    sgemm64_tf32_kernel<<<dim3(CC / 128, (BB * SS + 63) / 64), 256, sg64_smem>>>(
        xd, Wpq, q2, BB * SS, CC, CC, SCALE, nullptr);

    // 5) g = per-head W_pk @ q2  [tf32 TC, batched]
    g_tc_kernel<<<dim3((BB * SS) / 64, CC / 128, HH), 256, g_smem>>>(q2, Wpkv, gb);

    // 6) phase-2 attention
    phase2_kernel<<<BB * SS, 256, p2_smem>>>(traj, gb, pre, attn_ptr, write_attn);

    // 7) out = pre @ W_proj + b_proj  [tf32 TC, 64-tile high-occupancy]
    sgemm64_tf32_kernel<<<dim3(CC / 128, (BB * NTOK + 63) / 64), 256, sg64_smem>>>(
        pre, Wproj, (float*)d_out, BB * NTOK, CC, CC, 1.0f, bproj);
}